// round 13
// baseline (speedup 1.0000x reference)
#include <cuda_runtime.h>
#include <cuda_fp16.h>
#include <math.h>
#include <stdint.h>

#define D_MODEL 1024
#define D_INNER 2048
#define D_STATE 16
#define DT_RANK 64
#define NB 2
#define TSEQ 2048
#define MROWS (NB*TSEQ)   /* 4096 */
#define EPSV 1e-6f
#define XP_SPLIT 8

typedef __half fp16;

// ---------------- scratch (no allocations allowed) ----------------
__device__ fp16  g_xnh[MROWS*D_MODEL];
__device__ fp16  g_inwh[2*D_INNER*D_MODEL];
__device__ fp16  g_xpwh[96*D_INNER];
__device__ fp16  g_dtwh[D_INNER*DT_RANK];
__device__ fp16  g_opwh[D_MODEL*D_INNER];
__device__ float g_xz[MROWS*2*D_INNER];
__device__ fp16  g_xch[MROWS*D_INNER];
__device__ float g_xpp[XP_SPLIT*MROWS*96];
__device__ float g_xdbc[MROWS*96];
__device__ fp16  g_dth[MROWS*DT_RANK];
__device__ fp16  g_dch[MROWS*D_INNER];
__device__ fp16  g_yh[MROWS*D_INNER];

// ---------------- helpers ----------------
__device__ __forceinline__ uint32_t s2u(const void* p) {
    uint32_t a;
    asm("{ .reg .u64 t; cvta.to.shared.u64 t, %1; cvt.u32.u64 %0, t; }" : "=r"(a) : "l"(p));
    return a;
}
__device__ __forceinline__ void cpa16(uint32_t dst, const void* src) {
    asm volatile("cp.async.cg.shared.global [%0], [%1], 16;" :: "r"(dst), "l"(src) : "memory");
}
__device__ __forceinline__ void cpa16z(uint32_t dst, const void* src, int sz) {
    asm volatile("cp.async.cg.shared.global [%0], [%1], 16, %2;" :: "r"(dst), "l"(src), "r"(sz) : "memory");
}
#define CPA_COMMIT() asm volatile("cp.async.commit_group;" ::: "memory")

#define LDSM4(r, a) \
    asm volatile("ldmatrix.sync.aligned.m8n8.x4.shared.b16 {%0,%1,%2,%3}, [%4];" \
        : "=r"((r)[0]),"=r"((r)[1]),"=r"((r)[2]),"=r"((r)[3]) : "r"(a))

#define MMA16816(d, a, b0, b1) \
    asm volatile("mma.sync.aligned.m16n8k16.row.col.f32.f16.f16.f32 " \
        "{%0,%1,%2,%3}, {%4,%5,%6,%7}, {%8,%9}, {%0,%1,%2,%3};" \
        : "+f"((d)[0]),"+f"((d)[1]),"+f"((d)[2]),"+f"((d)[3]) \
        : "r"((a)[0]),"r"((a)[1]),"r"((a)[2]),"r"((a)[3]), "r"(b0),"r"(b1))

// ---------------- fp16 GEMM via mma.sync, deep half-chunk pipeline ----------------
// 128x128 tile, 3 stages of BK=64, half-chunk (BK=32) load/wait granularity.
// 256 threads = 8 warps (2x4), 2 CTAs/SM.
// EPI 0: C=v fp32   EPI 1: dc=clip(softplus(v+bias)) -> fp16 oh   EPI 2: C=v+res
#define GSMEM (3 * 32768)
template<int EPI>
__global__ __launch_bounds__(256, 2)
void gemm_mma(const fp16* __restrict__ A, const fp16* __restrict__ B,
              int K, int Nreal, int ldc,
              float* __restrict__ o0,
              const float* __restrict__ e0,
              fp16* __restrict__ oh)
{
    extern __shared__ char dyn[];
    const uint32_t sbase = s2u(dyn);
    const int tid = threadIdx.x, lane = tid & 31, wid = tid >> 5;
    const int wm = wid >> 2, wn = wid & 3;
    const int m0 = blockIdx.y * 128, n0 = blockIdx.x * 128;
    const int NH = K / 32;
    const int hc0 = 0, hc1 = NH;

    float acc[4][4][4];
    #pragma unroll
    for (int i = 0; i < 4; i++)
        #pragma unroll
        for (int j = 0; j < 4; j++)
            #pragma unroll
            for (int k = 0; k < 4; k++) acc[i][j][k] = 0.f;

    auto load_half = [&](int shc, int hc) {
        int fc = hc >> 1, hh = hc & 1;
        int kk = fc * 64;
        uint32_t st = sbase + ((shc >> 1) % 3) * 32768;
        #pragma unroll
        for (int j = 0; j < 2; j++) {
            int idx = tid + j * 256;
            int r = idx >> 2, c = idx & 3;
            int cl = 4 * hh + c;
            cpa16(st + r * 128 + ((cl ^ (r & 7)) * 16),
                  A + (size_t)(m0 + r) * K + kk + cl * 8);
        }
        uint32_t sb = st + 16384;
        #pragma unroll
        for (int j = 0; j < 2; j++) {
            int idx = tid + j * 256;
            int r = idx >> 2, c = idx & 3;
            int cl = 4 * hh + c;
            int nr = n0 + r;
            int ok = nr < Nreal;
            cpa16z(sb + r * 128 + ((cl ^ (r & 7)) * 16),
                   B + (size_t)(ok ? nr : 0) * K + kk + cl * 8, ok ? 16 : 0);
        }
    };

    #pragma unroll
    for (int p = 0; p < 4; p++) {
        if (hc0 + p < hc1) load_half(p, hc0 + p);
        CPA_COMMIT();
    }

    for (int hc = hc0; hc < hc1; hc++) {
        int shc = hc - hc0;
        asm volatile("cp.async.wait_group 3;" ::: "memory");
        __syncthreads();
        if (hc + 4 < hc1) load_half(shc + 4, hc + 4);
        CPA_COMMIT();

        uint32_t sA = sbase + ((shc >> 1) % 3) * 32768;
        uint32_t sB = sA + 16384;
        int hh = hc & 1;
        #pragma unroll
        for (int ks = 0; ks < 2; ks++) {
            int ksg = 2 * hh + ks;
            uint32_t a[4][4], b[2][4];
            #pragma unroll
            for (int mi = 0; mi < 4; mi++) {
                int r = wm * 64 + mi * 16 + (lane & 15);
                int c = (2 * ksg + (lane >> 4)) ^ (r & 7);
                LDSM4(a[mi], sA + r * 128 + c * 16);
            }
            #pragma unroll
            for (int g = 0; g < 2; g++) {
                int r = wn * 32 + g * 16 + (lane & 7) + ((lane >> 4) & 1) * 8;
                int c = (2 * ksg + ((lane >> 3) & 1)) ^ (r & 7);
                LDSM4(b[g], sB + r * 128 + c * 16);
            }
            #pragma unroll
            for (int mi = 0; mi < 4; mi++)
                #pragma unroll
                for (int nj = 0; nj < 4; nj++) {
                    int bg = nj >> 1, br = (nj & 1) * 2;
                    MMA16816(acc[mi][nj], a[mi], b[bg][br], b[bg][br+1]);
                }
        }
    }

    #pragma unroll
    for (int mi = 0; mi < 4; mi++)
        #pragma unroll
        for (int nj = 0; nj < 4; nj++)
            #pragma unroll
            for (int h = 0; h < 2; h++) {
                int m = m0 + wm*64 + mi*16 + (lane >> 2) + h*8;
                int nb = n0 + wn*32 + nj*8 + (lane & 3)*2;
                float vx = acc[mi][nj][h*2], vy = acc[mi][nj][h*2+1];
                size_t ci = (size_t)m * ldc + nb;
                if (EPI == 0) {
                    *(float2*)(o0 + ci) = make_float2(vx, vy);
                } else if (EPI == 1) {
                    vx += e0[nb]; vy += e0[nb+1];
                    float spx = (vx > 20.f) ? vx : log1pf(__expf(vx));
                    float spy = (vy > 20.f) ? vy : log1pf(__expf(vy));
                    float dx = fminf(fmaxf(spx, -10.f), 1.f);
                    float dy = fminf(fmaxf(spy, -10.f), 1.f);
                    __half2 hv; hv.x = __float2half(dx); hv.y = __float2half(dy);
                    *(__half2*)(oh + ci) = hv;
                } else {
                    float2 rv = *(const float2*)(e0 + ci);
                    *(float2*)(o0 + ci) = make_float2(vx + rv.x, vy + rv.y);
                }
            }
}

// ---------------- fused conv+silu+x_proj GEMM ----------------
// grid (1, 32, 8): y = m-tile (128 rows), z = channel slice (256 ch).
// A (= silu(conv(xz))) computed in-kernel from g_xz, STS'd for MMA and
// STG'd to g_xch. B (x_proj weights) fully prefetched via cp.async.
// smem: A 2x16KB alternating | B 4x16KB (full K-slice).
__global__ __launch_bounds__(256, 2)
void xproj_fused(const fp16* __restrict__ Bw,
                 const float* __restrict__ cw, const float* __restrict__ cb,
                 float* __restrict__ o0)
{
    extern __shared__ char dyn[];
    const uint32_t sbase = s2u(dyn);
    const int tid = threadIdx.x, lane = tid & 31, wid = tid >> 5;
    const int wm = wid >> 2, wn = wid & 3;
    const int m0 = blockIdx.y * 128;
    const int kbase = blockIdx.z * 256;

    float acc[4][4][4];
    #pragma unroll
    for (int i = 0; i < 4; i++)
        #pragma unroll
        for (int j = 0; j < 4; j++)
            #pragma unroll
            for (int k = 0; k < 4; k++) acc[i][j][k] = 0.f;

    // prologue: prefetch all 4 B chunks (96x64 fp16 each, padded to 128 rows)
    #pragma unroll
    for (int fc = 0; fc < 4; fc++) {
        uint32_t sb = sbase + 32768 + fc * 16384;
        #pragma unroll
        for (int j = 0; j < 2; j++) {
            int idx = tid + j * 256;
            int r = idx >> 2, c = idx & 3;
            // cover 8 slots with 2 passes of 4: use c and c+4
            int ok = r < 96;
            cpa16z(sb + r * 128 + (((c) ^ (r & 7)) * 16),
                   Bw + (size_t)(ok ? r : 0) * D_INNER + kbase + fc * 64 + c * 8, ok ? 16 : 0);
            cpa16z(sb + r * 128 + (((c + 4) ^ (r & 7)) * 16),
                   Bw + (size_t)(ok ? r : 0) * D_INNER + kbase + fc * 64 + (c + 4) * 8, ok ? 16 : 0);
        }
        CPA_COMMIT();
    }

    for (int fc = 0; fc < 4; fc++) {
        // ---- compute A chunk (conv+silu) into buffer fc&1, write g_xch ----
        uint32_t sA = sbase + (fc & 1) * 16384;
        #pragma unroll
        for (int j = 0; j < 4; j++) {
            int idx = tid + j * 256;            // 1024 slots: 128 rows x 8
            int r = idx >> 3, sl = idx & 7;
            int ch = kbase + fc * 64 + sl * 8;  // 8 channels
            int bt = m0 + r;
            int t = bt & (TSEQ - 1);
            float4 b0 = *(const float4*)(cb + ch);
            float4 b1 = *(const float4*)(cb + ch + 4);
            float a[8] = {b0.x,b0.y,b0.z,b0.w,b1.x,b1.y,b1.z,b1.w};
            #pragma unroll
            for (int k = 0; k < 4; k++) {
                if (t - 3 + k < 0) continue;
                const float* xr = g_xz + (size_t)(bt - 3 + k) * (2*D_INNER) + ch;
                float4 x0 = *(const float4*)xr;
                float4 x1 = *(const float4*)(xr + 4);
                float xv[8] = {x0.x,x0.y,x0.z,x0.w,x1.x,x1.y,x1.z,x1.w};
                #pragma unroll
                for (int q = 0; q < 8; q++)
                    a[q] = fmaf(cw[(ch + q)*4 + k], xv[q], a[q]);
            }
            __half2 hv[4];
            #pragma unroll
            for (int q = 0; q < 4; q++) {
                float o0v = a[2*q]   / (1.f + __expf(-a[2*q]));
                float o1v = a[2*q+1] / (1.f + __expf(-a[2*q+1]));
                hv[q].x = __float2half(o0v);
                hv[q].y = __float2half(o1v);
            }
            uint32_t da = sA + r * 128 + ((sl ^ (r & 7)) * 16);
            *(uint4*)((char*)dyn + (da - sbase)) = *(uint4*)hv;
            *(uint4*)(g_xch + (size_t)bt * D_INNER + ch) = *(uint4*)hv;
        }
        __syncthreads();
        // wait B chunk fc
        if (fc == 0)      asm volatile("cp.async.wait_group 3;" ::: "memory");
        else if (fc == 1) asm volatile("cp.async.wait_group 2;" ::: "memory");
        else if (fc == 2) asm volatile("cp.async.wait_group 1;" ::: "memory");
        else              asm volatile("cp.async.wait_group 0;" ::: "memory");
        __syncthreads();

        uint32_t sB = sbase + 32768 + fc * 16384;
        #pragma unroll
        for (int ks = 0; ks < 4; ks++) {
            uint32_t a[4][4], b[2][4];
            #pragma unroll
            for (int mi = 0; mi < 4; mi++) {
                int r = wm * 64 + mi * 16 + (lane & 15);
                int c = (2 * ks + (lane >> 4)) ^ (r & 7);
                LDSM4(a[mi], sA + r * 128 + c * 16);
            }
            #pragma unroll
            for (int g = 0; g < 2; g++) {
                int r = wn * 32 + g * 16 + (lane & 7) + ((lane >> 4) & 1) * 8;
                int c = (2 * ks + ((lane >> 3) & 1)) ^ (r & 7);
                LDSM4(b[g], sB + r * 128 + c * 16);
            }
            #pragma unroll
            for (int mi = 0; mi < 4; mi++)
                #pragma unroll
                for (int nj = 0; nj < 4; nj++) {
                    int bg = nj >> 1, br = (nj & 1) * 2;
                    MMA16816(acc[mi][nj], a[mi], b[bg][br], b[bg][br+1]);
                }
        }
        __syncthreads();
    }

    // ---- epilogue: split-K partial store ----
    #pragma unroll
    for (int mi = 0; mi < 4; mi++)
        #pragma unroll
        for (int nj = 0; nj < 4; nj++)
            #pragma unroll
            for (int h = 0; h < 2; h++) {
                int m = m0 + wm*64 + mi*16 + (lane >> 2) + h*8;
                int nb = wn*32 + nj*8 + (lane & 3)*2;
                if (nb < 96) {
                    *(float2*)(o0 + (size_t)blockIdx.z * MROWS * 96
                                  + (size_t)m * 96 + nb)
                        = make_float2(acc[mi][nj][h*2], acc[mi][nj][h*2+1]);
                }
            }
}

// ---------------- weight prep kernels ----------------
#define C1 (2*D_INNER*D_MODEL/4)
#define CR ((D_MODEL*D_INNER + 96*D_INNER + D_INNER*DT_RANK)/4)
__global__ void wprep_in(const float4* __restrict__ w_in) {
    int i = blockIdx.x * 256 + threadIdx.x;
    if (i >= C1) return;
    float4 v = w_in[i];
    __half2 p0, p1;
    p0.x = __float2half(v.x); p0.y = __float2half(v.y);
    p1.x = __float2half(v.z); p1.y = __float2half(v.w);
    *(__half2*)(g_inwh + (size_t)i * 4)     = p0;
    *(__half2*)(g_inwh + (size_t)i * 4 + 2) = p1;
}
__global__ void wprep_rest(const float4* __restrict__ w_op,
                           const float4* __restrict__ w_xp,
                           const float4* __restrict__ w_dt) {
    int i = blockIdx.x * 256 + threadIdx.x;
    if (i >= CR) return;
    const float4* src;
    fp16* hi;
    int j = i;
    const int R1 = D_MODEL*D_INNER/4, R2 = R1 + 96*D_INNER/4;
    if (i < R1)      { src = w_op; hi = g_opwh; }
    else if (i < R2) { src = w_xp; hi = g_xpwh; j = i - R1; }
    else             { src = w_dt; hi = g_dtwh; j = i - R2; }
    float4 v = src[j];
    __half2 p0, p1;
    p0.x = __float2half(v.x); p0.y = __float2half(v.y);
    p1.x = __float2half(v.z); p1.y = __float2half(v.w);
    *(__half2*)(hi + (size_t)j * 4)     = p0;
    *(__half2*)(hi + (size_t)j * 4 + 2) = p1;
}

// ---------------- rmsnorm ----------------
__global__ void rmsnorm_kernel(const float* __restrict__ x,
                               const float* __restrict__ w) {
    __shared__ float red[8];
    __shared__ float sscale;
    int row = blockIdx.x;
    int tid = threadIdx.x;
    const float4* xr = (const float4*)(x + (size_t)row * D_MODEL);
    float4 v = xr[tid];
    float ss = v.x*v.x + v.y*v.y + v.z*v.z + v.w*v.w;
    #pragma unroll
    for (int off = 16; off > 0; off >>= 1)
        ss += __shfl_xor_sync(0xffffffffu, ss, off);
    int lane = tid & 31, wq = tid >> 5;
    if (lane == 0) red[wq] = ss;
    __syncthreads();
    if (tid == 0) {
        float t = 0.f;
        #pragma unroll
        for (int i2 = 0; i2 < 8; i2++) t += red[i2];
        sscale = rsqrtf(t * (1.0f / D_MODEL) + EPSV);
    }
    __syncthreads();
    float sc = sscale;
    float4 wv = ((const float4*)w)[tid];
    float o0 = v.x*sc*wv.x, o1 = v.y*sc*wv.y, o2 = v.z*sc*wv.z, o3 = v.w*sc*wv.w;
    size_t base = (size_t)row * D_MODEL + tid * 4;
    __half2 ph0, ph1;
    ph0.x = __float2half(o0); ph0.y = __float2half(o1);
    ph1.x = __float2half(o2); ph1.y = __float2half(o3);
    *(__half2*)(g_xnh+base)   = ph0; *(__half2*)(g_xnh+base+2) = ph1;
}

// ---------------- x_proj partial reduce + dt fp16 ----------------
__global__ void xp_reduce_kernel() {
    int i = blockIdx.x * 256 + threadIdx.x;
    if (i >= MROWS * 96) return;
    float s = 0.f;
    #pragma unroll
    for (int z = 0; z < XP_SPLIT; z++)
        s += g_xpp[(size_t)z * MROWS * 96 + i];
    g_xdbc[i] = s;
    int m = i / 96, n = i - m * 96;
    if (n < 64) g_dth[m*64 + n] = __float2half(s);
}

// ---------------- selective scan ----------------
__global__ __launch_bounds__(256) void scan_kernel(const float* __restrict__ A_log,
                                                   const float* __restrict__ Dp) {
    __shared__ float2 sbc[64*16], sdd[64*16];
    __shared__ float se[64*16], sg[64*16];
    __shared__ float sP[16*16*20];
    int bid = blockIdx.x;
    int b = bid >> 7;
    int d0 = (bid & 127) << 4;
    int tid = threadIdx.x;
    int w = tid >> 5, lane = tid & 31;
    int s = lane & 15, half = lane >> 4;
    int cl = w * 2 + half;
    int d = d0 + cl;
    int jlo = tid & 15;
    int tl_r = tid >> 4, cl_r = tid & 15;
    float Aval = -__expf(A_log[d * D_STATE + s]);
    float Dvj = Dp[d0 + jlo];
    float h = 0.f;

    for (int t0 = 0; t0 < TSEQ; t0 += 64) {
        for (int i = tid; i < 1024; i += 256) {
            int ti = i >> 4, j = i & 15;
            size_t row = (size_t)b * TSEQ + t0 + ti;
            sbc[i] = make_float2(g_xdbc[row * 96 + 64 + j],
                                 g_xdbc[row * 96 + 80 + j]);
            float dcv = __half2float(g_dch[row * D_INNER + d0 + j]);
            float xcv = __half2float(g_xch[row * D_INNER + d0 + j]);
            sdd[i] = make_float2(dcv, dcv * xcv);
            se[i]  = xcv * Dvj;
            float zv = g_xz[row * (2*D_INNER) + D_INNER + d0 + j];
            sg[i]  = zv / (1.f + __expf(-zv));
        }
        __syncthreads();
        #pragma unroll
        for (int sub = 0; sub < 4; sub++) {
            #pragma unroll
            for (int i = 0; i < 16; i++) {
                int t = sub * 16 + i;
                float2 dd = sdd[t*16 + cl];
                float2 bc = sbc[t*16 + s];
                float r = __expf(dd.x * Aval);
                h = fmaf(r, h, dd.y * bc.x);
                sP[(i*16 + cl)*20 + s] = h * bc.y;
            }
            __syncthreads();
            {
                int base = (tl_r*16 + cl_r)*20;
                float4 va = *(const float4*)&sP[base];
                float4 vb = *(const float4*)&sP[base+4];
                float4 vc = *(const float4*)&sP[base+8];
                float4 vd = *(const float4*)&sP[base+12];
                float p = va.x+va.y+va.z+va.w + vb.x+vb.y+vb.z+vb.w
                        + vc.x+vc.y+vc.z+vc.w + vd.x+vd.y+vd.z+vd.w;
                int t = sub * 16 + tl_r;
                float yv = (p + se[t*16 + cl_r]) * sg[t*16 + cl_r];
                size_t row = (size_t)b * TSEQ + t0 + t;
                g_yh[row * D_INNER + d0 + cl_r] = __float2half(yv);
            }
            __syncthreads();
        }
    }
}

// ---------------- launch ----------------
extern "C" void kernel_launch(void* const* d_in, const int* in_sizes, int n_in,
                              void* d_out, int out_size) {
    (void)in_sizes; (void)n_in; (void)out_size;
    const float* x          = (const float*)d_in[0];
    const float* in_proj_w  = (const float*)d_in[1];
    const float* conv_w     = (const float*)d_in[2];
    const float* conv_b     = (const float*)d_in[3];
    const float* x_proj_w   = (const float*)d_in[4];
    const float* dt_proj_w  = (const float*)d_in[5];
    const float* dt_proj_b  = (const float*)d_in[6];
    const float* A_log      = (const float*)d_in[7];
    const float* Dp         = (const float*)d_in[8];
    const float* out_proj_w = (const float*)d_in[9];
    const float* norm_w     = (const float*)d_in[10];
    float* out = (float*)d_out;

    fp16 *xnh, *inwh, *xpwh, *dtwh, *opwh, *dth, *yh, *dch;
    float *xz, *xpp;
    cudaGetSymbolAddress((void**)&xnh,  g_xnh);
    cudaGetSymbolAddress((void**)&inwh, g_inwh);
    cudaGetSymbolAddress((void**)&xpwh, g_xpwh);
    cudaGetSymbolAddress((void**)&dtwh, g_dtwh);
    cudaGetSymbolAddress((void**)&opwh, g_opwh);
    cudaGetSymbolAddress((void**)&dth,  g_dth);
    cudaGetSymbolAddress((void**)&yh,   g_yh);
    cudaGetSymbolAddress((void**)&dch,  g_dch);
    cudaGetSymbolAddress((void**)&xz,   g_xz);
    cudaGetSymbolAddress((void**)&xpp,  g_xpp);

    cudaFuncSetAttribute((const void*)gemm_mma<0>, cudaFuncAttributeMaxDynamicSharedMemorySize, GSMEM);
    cudaFuncSetAttribute((const void*)gemm_mma<1>, cudaFuncAttributeMaxDynamicSharedMemorySize, GSMEM);
    cudaFuncSetAttribute((const void*)gemm_mma<2>, cudaFuncAttributeMaxDynamicSharedMemorySize, GSMEM);
    cudaFuncSetAttribute((const void*)xproj_fused, cudaFuncAttributeMaxDynamicSharedMemorySize, GSMEM);

    // 1. in_proj weight convert
    wprep_in<<<(C1 + 255)/256, 256>>>((const float4*)in_proj_w);
    // 2. other weight converts
    wprep_rest<<<(CR + 255)/256, 256>>>((const float4*)out_proj_w,
                                        (const float4*)x_proj_w,
                                        (const float4*)dt_proj_w);
    // 3. rmsnorm -> fp16
    rmsnorm_kernel<<<MROWS, 256>>>(x, norm_w);

    // 4. in_proj (profiled slot)
    gemm_mma<0><<<dim3(32, 32, 1), 256, GSMEM>>>(xnh, inwh,
        D_MODEL, 2*D_INNER, 2*D_INNER, xz, nullptr, nullptr);

    // 5. fused conv+silu+x_proj (split-K=8 partial buffers; also writes g_xch)
    xproj_fused<<<dim3(1, 32, XP_SPLIT), 256, GSMEM>>>(xpwh, conv_w, conv_b, xpp);

    // 6. reduce partials -> xdbc + dt fp16
    xp_reduce_kernel<<<(MROWS*96 + 255)/256, 256>>>();

    // 7. dt_proj (1-term) + softplus/clip -> dc fp16
    gemm_mma<1><<<dim3(16, 32, 1), 256, GSMEM>>>(dth, dtwh,
        DT_RANK, D_INNER, D_INNER, nullptr, dt_proj_b, dch);

    // 8. selective scan
    scan_kernel<<<NB * (D_INNER/16), 256>>>(A_log, Dp);

    // 9. out_proj (1-term fp16) + residual
    gemm_mma<2><<<dim3(8, 32, 1), 256, GSMEM>>>(yh, opwh,
        D_INNER, D_MODEL, D_MODEL, out, x, nullptr);
}

// round 14
// speedup vs baseline: 1.0644x; 1.0644x over previous
#include <cuda_runtime.h>
#include <cuda_fp16.h>
#include <math.h>
#include <stdint.h>

#define D_MODEL 1024
#define D_INNER 2048
#define D_STATE 16
#define DT_RANK 64
#define NB 2
#define TSEQ 2048
#define MROWS (NB*TSEQ)   /* 4096 */
#define EPSV 1e-6f
#define XP_SPLIT 8

typedef __half fp16;

// ---------------- scratch (no allocations allowed) ----------------
__device__ fp16  g_xnh[MROWS*D_MODEL];
__device__ fp16  g_inwh[2*D_INNER*D_MODEL];
__device__ fp16  g_xpwh[96*D_INNER];
__device__ fp16  g_dtwh[D_INNER*DT_RANK];
__device__ fp16  g_opwh[D_MODEL*D_INNER];
__device__ float g_xz[MROWS*2*D_INNER];
__device__ fp16  g_xch[MROWS*D_INNER];
__device__ float g_xpp[XP_SPLIT*MROWS*96];
__device__ float g_xdbc[MROWS*96];
__device__ fp16  g_dth[MROWS*DT_RANK];
__device__ fp16  g_dch[MROWS*D_INNER];
__device__ fp16  g_yh[MROWS*D_INNER];

// ---------------- helpers ----------------
__device__ __forceinline__ uint32_t s2u(const void* p) {
    uint32_t a;
    asm("{ .reg .u64 t; cvta.to.shared.u64 t, %1; cvt.u32.u64 %0, t; }" : "=r"(a) : "l"(p));
    return a;
}
__device__ __forceinline__ void cpa16(uint32_t dst, const void* src) {
    asm volatile("cp.async.cg.shared.global [%0], [%1], 16;" :: "r"(dst), "l"(src) : "memory");
}
__device__ __forceinline__ void cpa16z(uint32_t dst, const void* src, int sz) {
    asm volatile("cp.async.cg.shared.global [%0], [%1], 16, %2;" :: "r"(dst), "l"(src), "r"(sz) : "memory");
}
#define CPA_COMMIT() asm volatile("cp.async.commit_group;" ::: "memory")

#define LDSM4(r, a) \
    asm volatile("ldmatrix.sync.aligned.m8n8.x4.shared.b16 {%0,%1,%2,%3}, [%4];" \
        : "=r"((r)[0]),"=r"((r)[1]),"=r"((r)[2]),"=r"((r)[3]) : "r"(a))

#define MMA16816(d, a, b0, b1) \
    asm volatile("mma.sync.aligned.m16n8k16.row.col.f32.f16.f16.f32 " \
        "{%0,%1,%2,%3}, {%4,%5,%6,%7}, {%8,%9}, {%0,%1,%2,%3};" \
        : "+f"((d)[0]),"+f"((d)[1]),"+f"((d)[2]),"+f"((d)[3]) \
        : "r"((a)[0]),"r"((a)[1]),"r"((a)[2]),"r"((a)[3]), "r"(b0),"r"(b1))

// ---------------- fp16 GEMM via mma.sync (R8-proven full-chunk pipeline) ----------------
// 128x128 tile, BK=64, 3-stage ring, wait_group 1. 256 thr = 8 warps (2x4), 2 CTAs/SM.
// EPI 0: C=v fp32   EPI 1: dc=clip(softplus(v+bias)) -> fp16 oh
// EPI 2: C=v+res    EPI 4: split-K partial store
#define GSMEM (3 * 32768)
template<int EPI>
__global__ __launch_bounds__(256, 2)
void gemm_mma(const fp16* __restrict__ A, const fp16* __restrict__ B,
              int K, int Nreal, int ldc,
              float* __restrict__ o0,
              const float* __restrict__ e0,
              fp16* __restrict__ oh)
{
    extern __shared__ char dyn[];
    const uint32_t sbase = s2u(dyn);
    const int tid = threadIdx.x, lane = tid & 31, wid = tid >> 5;
    const int wm = wid >> 2, wn = wid & 3;
    const int m0 = blockIdx.y * 128, n0 = blockIdx.x * 128;
    const int NCtot = K / 64;
    const int per = (NCtot + gridDim.z - 1) / gridDim.z;
    const int kc0 = blockIdx.z * per;
    const int kc1 = min(NCtot, kc0 + per);

    float acc[4][4][4];
    #pragma unroll
    for (int i = 0; i < 4; i++)
        #pragma unroll
        for (int j = 0; j < 4; j++)
            #pragma unroll
            for (int k = 0; k < 4; k++) acc[i][j][k] = 0.f;

    auto load_stage = [&](int s, int kc) {
        int kk = kc * 64;
        uint32_t st = sbase + s * 32768;
        #pragma unroll
        for (int j = 0; j < 4; j++) {
            int idx = tid + j * 256;
            int r = idx >> 3, c = idx & 7;
            cpa16(st + r * 128 + ((c ^ (r & 7)) * 16),
                  A + (size_t)(m0 + r) * K + kk + c * 8);
        }
        uint32_t sb = st + 16384;
        #pragma unroll
        for (int j = 0; j < 4; j++) {
            int idx = tid + j * 256;
            int r = idx >> 3, c = idx & 7;
            int nr = n0 + r;
            int ok = nr < Nreal;
            cpa16z(sb + r * 128 + ((c ^ (r & 7)) * 16),
                   B + (size_t)(ok ? nr : 0) * K + kk + c * 8, ok ? 16 : 0);
        }
    };

    if (kc0 < kc1)     load_stage(0, kc0);
    CPA_COMMIT();
    if (kc0 + 1 < kc1) load_stage(1, kc0 + 1);
    CPA_COMMIT();

    for (int kc = kc0; kc < kc1; kc++) {
        int i = kc - kc0;
        int s = i % 3;
        asm volatile("cp.async.wait_group 1;" ::: "memory");
        __syncthreads();
        if (kc + 2 < kc1) load_stage((i + 2) % 3, kc + 2);
        CPA_COMMIT();

        uint32_t sA = sbase + s * 32768;
        uint32_t sB = sA + 16384;
        #pragma unroll
        for (int ks = 0; ks < 4; ks++) {
            uint32_t a[4][4], b[2][4];
            #pragma unroll
            for (int mi = 0; mi < 4; mi++) {
                int r = wm * 64 + mi * 16 + (lane & 15);
                int c = (2 * ks + (lane >> 4)) ^ (r & 7);
                LDSM4(a[mi], sA + r * 128 + c * 16);
            }
            #pragma unroll
            for (int g = 0; g < 2; g++) {
                int r = wn * 32 + g * 16 + (lane & 7) + ((lane >> 4) & 1) * 8;
                int c = (2 * ks + ((lane >> 3) & 1)) ^ (r & 7);
                LDSM4(b[g], sB + r * 128 + c * 16);
            }
            #pragma unroll
            for (int mi = 0; mi < 4; mi++)
                #pragma unroll
                for (int nj = 0; nj < 4; nj++) {
                    int bg = nj >> 1, br = (nj & 1) * 2;
                    MMA16816(acc[mi][nj], a[mi], b[bg][br], b[bg][br+1]);
                }
        }
    }

    // ---- epilogue straight from registers ----
    #pragma unroll
    for (int mi = 0; mi < 4; mi++)
        #pragma unroll
        for (int nj = 0; nj < 4; nj++)
            #pragma unroll
            for (int h = 0; h < 2; h++) {
                int m = m0 + wm*64 + mi*16 + (lane >> 2) + h*8;
                int nb = n0 + wn*32 + nj*8 + (lane & 3)*2;
                float vx = acc[mi][nj][h*2], vy = acc[mi][nj][h*2+1];
                size_t ci = (size_t)m * ldc + nb;
                if (EPI == 0) {
                    *(float2*)(o0 + ci) = make_float2(vx, vy);
                } else if (EPI == 1) {
                    vx += e0[nb]; vy += e0[nb+1];
                    float spx = (vx > 20.f) ? vx : log1pf(__expf(vx));
                    float spy = (vy > 20.f) ? vy : log1pf(__expf(vy));
                    float dx = fminf(fmaxf(spx, -10.f), 1.f);
                    float dy = fminf(fmaxf(spy, -10.f), 1.f);
                    __half2 hv; hv.x = __float2half(dx); hv.y = __float2half(dy);
                    *(__half2*)(oh + ci) = hv;
                } else if (EPI == 2) {
                    float2 rv = *(const float2*)(e0 + ci);
                    *(float2*)(o0 + ci) = make_float2(vx + rv.x, vy + rv.y);
                } else {
                    if (nb < Nreal) {
                        *(float2*)(o0 + (size_t)blockIdx.z * MROWS * 96
                                      + (size_t)m * 96 + nb) = make_float2(vx, vy);
                    }
                }
            }
}

// ---------------- weight prep kernels (split so in_proj stays in profiler slot 4) ----------------
#define C1 (2*D_INNER*D_MODEL/4)
#define CR ((D_MODEL*D_INNER + 96*D_INNER + D_INNER*DT_RANK)/4)
__global__ void wprep_in(const float4* __restrict__ w_in) {
    int i = blockIdx.x * 256 + threadIdx.x;
    if (i >= C1) return;
    float4 v = w_in[i];
    __half2 p0, p1;
    p0.x = __float2half(v.x); p0.y = __float2half(v.y);
    p1.x = __float2half(v.z); p1.y = __float2half(v.w);
    *(__half2*)(g_inwh + (size_t)i * 4)     = p0;
    *(__half2*)(g_inwh + (size_t)i * 4 + 2) = p1;
}
__global__ void wprep_rest(const float4* __restrict__ w_op,
                           const float4* __restrict__ w_xp,
                           const float4* __restrict__ w_dt) {
    int i = blockIdx.x * 256 + threadIdx.x;
    if (i >= CR) return;
    const float4* src;
    fp16* hi;
    int j = i;
    const int R1 = D_MODEL*D_INNER/4, R2 = R1 + 96*D_INNER/4;
    if (i < R1)      { src = w_op; hi = g_opwh; }
    else if (i < R2) { src = w_xp; hi = g_xpwh; j = i - R1; }
    else             { src = w_dt; hi = g_dtwh; j = i - R2; }
    float4 v = src[j];
    __half2 p0, p1;
    p0.x = __float2half(v.x); p0.y = __float2half(v.y);
    p1.x = __float2half(v.z); p1.y = __float2half(v.w);
    *(__half2*)(hi + (size_t)j * 4)     = p0;
    *(__half2*)(hi + (size_t)j * 4 + 2) = p1;
}

// ---------------- rmsnorm ----------------
__global__ void rmsnorm_kernel(const float* __restrict__ x,
                               const float* __restrict__ w) {
    __shared__ float red[8];
    __shared__ float sscale;
    int row = blockIdx.x;
    int tid = threadIdx.x;
    const float4* xr = (const float4*)(x + (size_t)row * D_MODEL);
    float4 v = xr[tid];
    float ss = v.x*v.x + v.y*v.y + v.z*v.z + v.w*v.w;
    #pragma unroll
    for (int off = 16; off > 0; off >>= 1)
        ss += __shfl_xor_sync(0xffffffffu, ss, off);
    int lane = tid & 31, wq = tid >> 5;
    if (lane == 0) red[wq] = ss;
    __syncthreads();
    if (tid == 0) {
        float t = 0.f;
        #pragma unroll
        for (int i2 = 0; i2 < 8; i2++) t += red[i2];
        sscale = rsqrtf(t * (1.0f / D_MODEL) + EPSV);
    }
    __syncthreads();
    float sc = sscale;
    float4 wv = ((const float4*)w)[tid];
    float o0 = v.x*sc*wv.x, o1 = v.y*sc*wv.y, o2 = v.z*sc*wv.z, o3 = v.w*sc*wv.w;
    size_t base = (size_t)row * D_MODEL + tid * 4;
    __half2 ph0, ph1;
    ph0.x = __float2half(o0); ph0.y = __float2half(o1);
    ph1.x = __float2half(o2); ph1.y = __float2half(o3);
    *(__half2*)(g_xnh+base)   = ph0; *(__half2*)(g_xnh+base+2) = ph1;
}

// ---------------- depthwise causal conv(4) + silu -> fp16 ----------------
__global__ void conv_silu_kernel(const float* __restrict__ cw,
                                 const float* __restrict__ cb) {
    int idx = blockIdx.x * 256 + threadIdx.x;
    if (idx >= MROWS * (D_INNER/4)) return;
    int d4 = idx & (D_INNER/4 - 1);
    int bt = idx >> 9;
    int t  = bt & (TSEQ - 1);
    int d  = d4 * 4;
    float wv[4][4];
    *(float4*)wv[0] = *(const float4*)(cw + (d+0)*4);
    *(float4*)wv[1] = *(const float4*)(cw + (d+1)*4);
    *(float4*)wv[2] = *(const float4*)(cw + (d+2)*4);
    *(float4*)wv[3] = *(const float4*)(cw + (d+3)*4);
    float4 bvv = *(const float4*)(cb + d);
    float a0 = bvv.x, a1 = bvv.y, a2 = bvv.z, a3 = bvv.w;
    #pragma unroll
    for (int k = 0; k < 4; k++) {
        int tt = t - 3 + k;
        if (tt < 0) continue;
        const float4 xv = *(const float4*)(g_xz + (size_t)(bt - t + tt) * (2*D_INNER) + d);
        a0 = fmaf(wv[0][k], xv.x, a0);
        a1 = fmaf(wv[1][k], xv.y, a1);
        a2 = fmaf(wv[2][k], xv.z, a2);
        a3 = fmaf(wv[3][k], xv.w, a3);
    }
    float o0 = a0/(1.f+__expf(-a0)), o1 = a1/(1.f+__expf(-a1));
    float o2 = a2/(1.f+__expf(-a2)), o3 = a3/(1.f+__expf(-a3));
    size_t base = (size_t)bt * D_INNER + d;
    __half2 ph0, ph1;
    ph0.x = __float2half(o0); ph0.y = __float2half(o1);
    ph1.x = __float2half(o2); ph1.y = __float2half(o3);
    *(__half2*)(g_xch+base)   = ph0; *(__half2*)(g_xch+base+2) = ph1;
}

// ---------------- x_proj partial reduce + dt fp16 ----------------
__global__ void xp_reduce_kernel() {
    int i = blockIdx.x * 256 + threadIdx.x;
    if (i >= MROWS * 96) return;
    float s = 0.f;
    #pragma unroll
    for (int z = 0; z < XP_SPLIT; z++)
        s += g_xpp[(size_t)z * MROWS * 96 + i];
    g_xdbc[i] = s;
    int m = i / 96, n = i - m * 96;
    if (n < 64) g_dth[m*64 + n] = __float2half(s);
}

// ---------------- selective scan (packed float2 staging, float4 reduction) ----------------
__global__ __launch_bounds__(256) void scan_kernel(const float* __restrict__ A_log,
                                                   const float* __restrict__ Dp) {
    __shared__ float2 sbc[64*16], sdd[64*16];
    __shared__ float se[64*16], sg[64*16];
    __shared__ float sP[16*16*20];
    int bid = blockIdx.x;
    int b = bid >> 7;
    int d0 = (bid & 127) << 4;
    int tid = threadIdx.x;
    int w = tid >> 5, lane = tid & 31;
    int s = lane & 15, half = lane >> 4;
    int cl = w * 2 + half;
    int d = d0 + cl;
    int jlo = tid & 15;
    int tl_r = tid >> 4, cl_r = tid & 15;
    float Aval = -__expf(A_log[d * D_STATE + s]);
    float Dvj = Dp[d0 + jlo];
    float h = 0.f;

    for (int t0 = 0; t0 < TSEQ; t0 += 64) {
        for (int i = tid; i < 1024; i += 256) {
            int ti = i >> 4, j = i & 15;
            size_t row = (size_t)b * TSEQ + t0 + ti;
            sbc[i] = make_float2(g_xdbc[row * 96 + 64 + j],
                                 g_xdbc[row * 96 + 80 + j]);
            float dcv = __half2float(g_dch[row * D_INNER + d0 + j]);
            float xcv = __half2float(g_xch[row * D_INNER + d0 + j]);
            sdd[i] = make_float2(dcv, dcv * xcv);
            se[i]  = xcv * Dvj;
            float zv = g_xz[row * (2*D_INNER) + D_INNER + d0 + j];
            sg[i]  = zv / (1.f + __expf(-zv));
        }
        __syncthreads();
        #pragma unroll
        for (int sub = 0; sub < 4; sub++) {
            #pragma unroll
            for (int i = 0; i < 16; i++) {
                int t = sub * 16 + i;
                float2 dd = sdd[t*16 + cl];
                float2 bc = sbc[t*16 + s];
                float r = __expf(dd.x * Aval);
                h = fmaf(r, h, dd.y * bc.x);
                sP[(i*16 + cl)*20 + s] = h * bc.y;
            }
            __syncthreads();
            {
                int base = (tl_r*16 + cl_r)*20;
                float4 va = *(const float4*)&sP[base];
                float4 vb = *(const float4*)&sP[base+4];
                float4 vc = *(const float4*)&sP[base+8];
                float4 vd = *(const float4*)&sP[base+12];
                float p = va.x+va.y+va.z+va.w + vb.x+vb.y+vb.z+vb.w
                        + vc.x+vc.y+vc.z+vc.w + vd.x+vd.y+vd.z+vd.w;
                int t = sub * 16 + tl_r;
                float yv = (p + se[t*16 + cl_r]) * sg[t*16 + cl_r];
                size_t row = (size_t)b * TSEQ + t0 + t;
                g_yh[row * D_INNER + d0 + cl_r] = __float2half(yv);
            }
            __syncthreads();
        }
    }
}

// ---------------- launch ----------------
extern "C" void kernel_launch(void* const* d_in, const int* in_sizes, int n_in,
                              void* d_out, int out_size) {
    (void)in_sizes; (void)n_in; (void)out_size;
    const float* x          = (const float*)d_in[0];
    const float* in_proj_w  = (const float*)d_in[1];
    const float* conv_w     = (const float*)d_in[2];
    const float* conv_b     = (const float*)d_in[3];
    const float* x_proj_w   = (const float*)d_in[4];
    const float* dt_proj_w  = (const float*)d_in[5];
    const float* dt_proj_b  = (const float*)d_in[6];
    const float* A_log      = (const float*)d_in[7];
    const float* Dp         = (const float*)d_in[8];
    const float* out_proj_w = (const float*)d_in[9];
    const float* norm_w     = (const float*)d_in[10];
    float* out = (float*)d_out;

    fp16 *xnh, *inwh, *xpwh, *dtwh, *opwh, *xch, *dth, *yh, *dch;
    float *xz, *xpp;
    cudaGetSymbolAddress((void**)&xnh,  g_xnh);
    cudaGetSymbolAddress((void**)&inwh, g_inwh);
    cudaGetSymbolAddress((void**)&xpwh, g_xpwh);
    cudaGetSymbolAddress((void**)&dtwh, g_dtwh);
    cudaGetSymbolAddress((void**)&opwh, g_opwh);
    cudaGetSymbolAddress((void**)&xch,  g_xch);
    cudaGetSymbolAddress((void**)&dth,  g_dth);
    cudaGetSymbolAddress((void**)&yh,   g_yh);
    cudaGetSymbolAddress((void**)&dch,  g_dch);
    cudaGetSymbolAddress((void**)&xz,   g_xz);
    cudaGetSymbolAddress((void**)&xpp,  g_xpp);

    cudaFuncSetAttribute((const void*)gemm_mma<0>, cudaFuncAttributeMaxDynamicSharedMemorySize, GSMEM);
    cudaFuncSetAttribute((const void*)gemm_mma<1>, cudaFuncAttributeMaxDynamicSharedMemorySize, GSMEM);
    cudaFuncSetAttribute((const void*)gemm_mma<2>, cudaFuncAttributeMaxDynamicSharedMemorySize, GSMEM);
    cudaFuncSetAttribute((const void*)gemm_mma<4>, cudaFuncAttributeMaxDynamicSharedMemorySize, GSMEM);

    // 1. in_proj weight convert
    wprep_in<<<(C1 + 255)/256, 256>>>((const float4*)in_proj_w);
    // 2. other weight converts
    wprep_rest<<<(CR + 255)/256, 256>>>((const float4*)out_proj_w,
                                        (const float4*)x_proj_w,
                                        (const float4*)dt_proj_w);
    // 3. rmsnorm -> fp16
    rmsnorm_kernel<<<MROWS, 256>>>(x, norm_w);

    // 4. in_proj (profiled slot 4) -> xz fp32
    gemm_mma<0><<<dim3(32, 32, 1), 256, GSMEM>>>(xnh, inwh,
        D_MODEL, 2*D_INNER, 2*D_INNER, xz, nullptr, nullptr);

    // 5. conv + silu -> xch fp16
    conv_silu_kernel<<<(MROWS * (D_INNER/4) + 255)/256, 256>>>(conv_w, conv_b);

    // 6. x_proj (1-term, split-K=8 -> partial buffers)
    gemm_mma<4><<<dim3(1, 32, XP_SPLIT), 256, GSMEM>>>(xch, xpwh,
        D_INNER, 96, 96, xpp, nullptr, nullptr);

    // 7. reduce partials -> xdbc + dt fp16
    xp_reduce_kernel<<<(MROWS*96 + 255)/256, 256>>>();

    // 8. dt_proj (1-term) + softplus/clip -> dc fp16
    gemm_mma<1><<<dim3(16, 32, 1), 256, GSMEM>>>(dth, dtwh,
        DT_RANK, D_INNER, D_INNER, nullptr, dt_proj_b, dch);

    // 9. selective scan
    scan_kernel<<<NB * (D_INNER/16), 256>>>(A_log, Dp);

    // 10. out_proj (1-term fp16) + residual
    gemm_mma<2><<<dim3(8, 32, 1), 256, GSMEM>>>(yh, opwh,
        D_INNER, D_MODEL, D_MODEL, out, x, nullptr);
}

// round 15
// speedup vs baseline: 1.1320x; 1.0635x over previous
#include <cuda_runtime.h>
#include <cuda_fp16.h>
#include <math.h>
#include <stdint.h>

#define D_MODEL 1024
#define D_INNER 2048
#define D_STATE 16
#define DT_RANK 64
#define NB 2
#define TSEQ 2048
#define MROWS (NB*TSEQ)   /* 4096 */
#define EPSV 1e-6f
#define XP_SPLIT 8

typedef __half fp16;

// ---------------- scratch (no allocations allowed) ----------------
__device__ fp16  g_xnh[MROWS*D_MODEL];
__device__ fp16  g_inwh[2*D_INNER*D_MODEL];
__device__ fp16  g_xpwh[96*D_INNER];
__device__ fp16  g_dtwh[D_INNER*DT_RANK];
__device__ fp16  g_opwh[D_MODEL*D_INNER];
__device__ float g_xz[MROWS*2*D_INNER];
__device__ fp16  g_xch[MROWS*D_INNER];
__device__ float g_xpp[XP_SPLIT*MROWS*96];
__device__ float g_xdbc[MROWS*96];
__device__ fp16  g_dth[MROWS*DT_RANK];
__device__ fp16  g_dch[MROWS*D_INNER];
__device__ fp16  g_yh[MROWS*D_INNER];

// ---------------- helpers ----------------
__device__ __forceinline__ uint32_t s2u(const void* p) {
    uint32_t a;
    asm("{ .reg .u64 t; cvta.to.shared.u64 t, %1; cvt.u32.u64 %0, t; }" : "=r"(a) : "l"(p));
    return a;
}
__device__ __forceinline__ void cpa16(uint32_t dst, const void* src) {
    asm volatile("cp.async.cg.shared.global [%0], [%1], 16;" :: "r"(dst), "l"(src) : "memory");
}
__device__ __forceinline__ void cpa16z(uint32_t dst, const void* src, int sz) {
    asm volatile("cp.async.cg.shared.global [%0], [%1], 16, %2;" :: "r"(dst), "l"(src), "r"(sz) : "memory");
}
#define CPA_COMMIT() asm volatile("cp.async.commit_group;" ::: "memory")

#define LDSM4(r, a) \
    asm volatile("ldmatrix.sync.aligned.m8n8.x4.shared.b16 {%0,%1,%2,%3}, [%4];" \
        : "=r"((r)[0]),"=r"((r)[1]),"=r"((r)[2]),"=r"((r)[3]) : "r"(a))

#define MMA16816(d, a, b0, b1) \
    asm volatile("mma.sync.aligned.m16n8k16.row.col.f32.f16.f16.f32 " \
        "{%0,%1,%2,%3}, {%4,%5,%6,%7}, {%8,%9}, {%0,%1,%2,%3};" \
        : "+f"((d)[0]),"+f"((d)[1]),"+f"((d)[2]),"+f"((d)[3]) \
        : "r"((a)[0]),"r"((a)[1]),"r"((a)[2]),"r"((a)[3]), "r"(b0),"r"(b1))

// ---------------- fp16 GEMM via mma.sync (R8-proven full-chunk pipeline) ----------------
#define GSMEM (3 * 32768)
template<int EPI>
__global__ __launch_bounds__(256, 2)
void gemm_mma(const fp16* __restrict__ A, const fp16* __restrict__ B,
              int K, int Nreal, int ldc,
              float* __restrict__ o0,
              const float* __restrict__ e0,
              fp16* __restrict__ oh)
{
    extern __shared__ char dyn[];
    const uint32_t sbase = s2u(dyn);
    const int tid = threadIdx.x, lane = tid & 31, wid = tid >> 5;
    const int wm = wid >> 2, wn = wid & 3;
    const int m0 = blockIdx.y * 128, n0 = blockIdx.x * 128;
    const int NCtot = K / 64;
    const int per = (NCtot + gridDim.z - 1) / gridDim.z;
    const int kc0 = blockIdx.z * per;
    const int kc1 = min(NCtot, kc0 + per);

    float acc[4][4][4];
    #pragma unroll
    for (int i = 0; i < 4; i++)
        #pragma unroll
        for (int j = 0; j < 4; j++)
            #pragma unroll
            for (int k = 0; k < 4; k++) acc[i][j][k] = 0.f;

    auto load_stage = [&](int s, int kc) {
        int kk = kc * 64;
        uint32_t st = sbase + s * 32768;
        #pragma unroll
        for (int j = 0; j < 4; j++) {
            int idx = tid + j * 256;
            int r = idx >> 3, c = idx & 7;
            cpa16(st + r * 128 + ((c ^ (r & 7)) * 16),
                  A + (size_t)(m0 + r) * K + kk + c * 8);
        }
        uint32_t sb = st + 16384;
        #pragma unroll
        for (int j = 0; j < 4; j++) {
            int idx = tid + j * 256;
            int r = idx >> 3, c = idx & 7;
            int nr = n0 + r;
            int ok = nr < Nreal;
            cpa16z(sb + r * 128 + ((c ^ (r & 7)) * 16),
                   B + (size_t)(ok ? nr : 0) * K + kk + c * 8, ok ? 16 : 0);
        }
    };

    if (kc0 < kc1)     load_stage(0, kc0);
    CPA_COMMIT();
    if (kc0 + 1 < kc1) load_stage(1, kc0 + 1);
    CPA_COMMIT();

    for (int kc = kc0; kc < kc1; kc++) {
        int i = kc - kc0;
        int s = i % 3;
        asm volatile("cp.async.wait_group 1;" ::: "memory");
        __syncthreads();
        if (kc + 2 < kc1) load_stage((i + 2) % 3, kc + 2);
        CPA_COMMIT();

        uint32_t sA = sbase + s * 32768;
        uint32_t sB = sA + 16384;
        #pragma unroll
        for (int ks = 0; ks < 4; ks++) {
            uint32_t a[4][4], b[2][4];
            #pragma unroll
            for (int mi = 0; mi < 4; mi++) {
                int r = wm * 64 + mi * 16 + (lane & 15);
                int c = (2 * ks + (lane >> 4)) ^ (r & 7);
                LDSM4(a[mi], sA + r * 128 + c * 16);
            }
            #pragma unroll
            for (int g = 0; g < 2; g++) {
                int r = wn * 32 + g * 16 + (lane & 7) + ((lane >> 4) & 1) * 8;
                int c = (2 * ks + ((lane >> 3) & 1)) ^ (r & 7);
                LDSM4(b[g], sB + r * 128 + c * 16);
            }
            #pragma unroll
            for (int mi = 0; mi < 4; mi++)
                #pragma unroll
                for (int nj = 0; nj < 4; nj++) {
                    int bg = nj >> 1, br = (nj & 1) * 2;
                    MMA16816(acc[mi][nj], a[mi], b[bg][br], b[bg][br+1]);
                }
        }
    }

    #pragma unroll
    for (int mi = 0; mi < 4; mi++)
        #pragma unroll
        for (int nj = 0; nj < 4; nj++)
            #pragma unroll
            for (int h = 0; h < 2; h++) {
                int m = m0 + wm*64 + mi*16 + (lane >> 2) + h*8;
                int nb = n0 + wn*32 + nj*8 + (lane & 3)*2;
                float vx = acc[mi][nj][h*2], vy = acc[mi][nj][h*2+1];
                size_t ci = (size_t)m * ldc + nb;
                if (EPI == 0) {
                    *(float2*)(o0 + ci) = make_float2(vx, vy);
                } else if (EPI == 1) {
                    vx += e0[nb]; vy += e0[nb+1];
                    float spx = (vx > 20.f) ? vx : log1pf(__expf(vx));
                    float spy = (vy > 20.f) ? vy : log1pf(__expf(vy));
                    float dx = fminf(fmaxf(spx, -10.f), 1.f);
                    float dy = fminf(fmaxf(spy, -10.f), 1.f);
                    __half2 hv; hv.x = __float2half(dx); hv.y = __float2half(dy);
                    *(__half2*)(oh + ci) = hv;
                } else if (EPI == 2) {
                    float2 rv = *(const float2*)(e0 + ci);
                    *(float2*)(o0 + ci) = make_float2(vx + rv.x, vy + rv.y);
                } else {
                    if (nb < Nreal) {
                        *(float2*)(o0 + (size_t)blockIdx.z * MROWS * 96
                                      + (size_t)m * 96 + nb) = make_float2(vx, vy);
                    }
                }
            }
}

// ---------------- weight prep: in_proj separate (keeps conv in profiler slot 4) ----------------
#define C1 (2*D_INNER*D_MODEL/4)
#define CR ((D_MODEL*D_INNER + 96*D_INNER + D_INNER*DT_RANK)/4)
#define CRB ((CR + 255) / 256)
__global__ void wprep_in(const float4* __restrict__ w_in) {
    int i = blockIdx.x * 256 + threadIdx.x;
    if (i >= C1) return;
    float4 v = w_in[i];
    __half2 p0, p1;
    p0.x = __float2half(v.x); p0.y = __float2half(v.y);
    p1.x = __float2half(v.z); p1.y = __float2half(v.w);
    *(__half2*)(g_inwh + (size_t)i * 4)     = p0;
    *(__half2*)(g_inwh + (size_t)i * 4 + 2) = p1;
}

// wprep_rest + rmsnorm merged (blockIdx dispatch)
__global__ void wprep_rest_rms(const float4* __restrict__ w_op,
                               const float4* __restrict__ w_xp,
                               const float4* __restrict__ w_dt,
                               const float* __restrict__ x,
                               const float* __restrict__ w_norm) {
    __shared__ float red[8];
    __shared__ float sscale;
    int bx = blockIdx.x;
    if (bx < CRB) {
        int i = bx * 256 + threadIdx.x;
        if (i >= CR) return;
        const float4* src;
        fp16* hi;
        int j = i;
        const int R1 = D_MODEL*D_INNER/4, R2 = R1 + 96*D_INNER/4;
        if (i < R1)      { src = w_op; hi = g_opwh; }
        else if (i < R2) { src = w_xp; hi = g_xpwh; j = i - R1; }
        else             { src = w_dt; hi = g_dtwh; j = i - R2; }
        float4 v = src[j];
        __half2 p0, p1;
        p0.x = __float2half(v.x); p0.y = __float2half(v.y);
        p1.x = __float2half(v.z); p1.y = __float2half(v.w);
        *(__half2*)(hi + (size_t)j * 4)     = p0;
        *(__half2*)(hi + (size_t)j * 4 + 2) = p1;
    } else {
        int row = bx - CRB;
        int tid = threadIdx.x;
        const float4* xr = (const float4*)(x + (size_t)row * D_MODEL);
        float4 v = xr[tid];
        float ss = v.x*v.x + v.y*v.y + v.z*v.z + v.w*v.w;
        #pragma unroll
        for (int off = 16; off > 0; off >>= 1)
            ss += __shfl_xor_sync(0xffffffffu, ss, off);
        int lane = tid & 31, wq = tid >> 5;
        if (lane == 0) red[wq] = ss;
        __syncthreads();
        if (tid == 0) {
            float t = 0.f;
            #pragma unroll
            for (int i2 = 0; i2 < 8; i2++) t += red[i2];
            sscale = rsqrtf(t * (1.0f / D_MODEL) + EPSV);
        }
        __syncthreads();
        float sc = sscale;
        float4 wv = ((const float4*)w_norm)[tid];
        float o0 = v.x*sc*wv.x, o1 = v.y*sc*wv.y, o2 = v.z*sc*wv.z, o3 = v.w*sc*wv.w;
        size_t base = (size_t)row * D_MODEL + tid * 4;
        __half2 ph0, ph1;
        ph0.x = __float2half(o0); ph0.y = __float2half(o1);
        ph1.x = __float2half(o2); ph1.y = __float2half(o3);
        *(__half2*)(g_xnh+base)   = ph0; *(__half2*)(g_xnh+base+2) = ph1;
    }
}

// ---------------- tiled depthwise causal conv(4) + silu -> fp16 ----------------
// grid = (MROWS/64) * 16 blocks; block = 64 t-rows x 128 channels.
// Input x-half staged in smem (1x read amplification). Identical fp32 math.
__global__ __launch_bounds__(256) void conv_tiled(const float* __restrict__ cw,
                                                  const float* __restrict__ cb) {
    __shared__ float sx[67*128];        // 34 KB
    int db = blockIdx.x & 15, tb = blockIdx.x >> 4;
    int t0 = tb * 64;                   // global row base
    int d0 = db * 128;
    int tid = threadIdx.x;
    int tinb = t0 & (TSEQ - 1);         // t within batch
    for (int idx = tid; idx < 67*32; idx += 256) {
        int r = idx >> 5, c = idx & 31;
        int tloc = tinb - 3 + r;
        float4 v = make_float4(0.f, 0.f, 0.f, 0.f);
        if (tloc >= 0 && tloc < TSEQ)
            v = *(const float4*)(g_xz + (size_t)(t0 - 3 + r) * (2*D_INNER) + d0 + c*4);
        *(float4*)&sx[r*128 + c*4] = v;
    }
    __syncthreads();
    int j = tid & 31;                   // ch4 index 0..31
    int i0 = (tid >> 5) * 8;            // 8 t's per thread
    int d = d0 + j*4;
    float wv[4][4];
    *(float4*)wv[0] = *(const float4*)(cw + (d+0)*4);
    *(float4*)wv[1] = *(const float4*)(cw + (d+1)*4);
    *(float4*)wv[2] = *(const float4*)(cw + (d+2)*4);
    *(float4*)wv[3] = *(const float4*)(cw + (d+3)*4);
    float4 bvv = *(const float4*)(cb + d);
    #pragma unroll
    for (int rep = 0; rep < 8; rep++) {
        int i = i0 + rep;
        float a0 = bvv.x, a1 = bvv.y, a2 = bvv.z, a3 = bvv.w;
        #pragma unroll
        for (int k = 0; k < 4; k++) {
            float4 xv = *(float4*)&sx[(i+k)*128 + j*4];
            a0 = fmaf(wv[0][k], xv.x, a0);
            a1 = fmaf(wv[1][k], xv.y, a1);
            a2 = fmaf(wv[2][k], xv.z, a2);
            a3 = fmaf(wv[3][k], xv.w, a3);
        }
        float o0 = a0/(1.f+__expf(-a0)), o1 = a1/(1.f+__expf(-a1));
        float o2 = a2/(1.f+__expf(-a2)), o3 = a3/(1.f+__expf(-a3));
        __half2 hv[2];
        hv[0].x = __float2half(o0); hv[0].y = __float2half(o1);
        hv[1].x = __float2half(o2); hv[1].y = __float2half(o3);
        *(uint2*)(g_xch + (size_t)(t0 + i) * D_INNER + d) = *(uint2*)hv;
    }
}

// ---------------- x_proj partial reduce + dt fp16 ----------------
__global__ void xp_reduce_kernel() {
    int i = blockIdx.x * 256 + threadIdx.x;
    if (i >= MROWS * 96) return;
    float s = 0.f;
    #pragma unroll
    for (int z = 0; z < XP_SPLIT; z++)
        s += g_xpp[(size_t)z * MROWS * 96 + i];
    g_xdbc[i] = s;
    int m = i / 96, n = i - m * 96;
    if (n < 64) g_dth[m*64 + n] = __float2half(s);
}

// ---------------- selective scan (packed float2 staging, float4 reduction) ----------------
__global__ __launch_bounds__(256) void scan_kernel(const float* __restrict__ A_log,
                                                   const float* __restrict__ Dp) {
    __shared__ float2 sbc[64*16], sdd[64*16];
    __shared__ float se[64*16], sg[64*16];
    __shared__ float sP[16*16*20];
    int bid = blockIdx.x;
    int b = bid >> 7;
    int d0 = (bid & 127) << 4;
    int tid = threadIdx.x;
    int w = tid >> 5, lane = tid & 31;
    int s = lane & 15, half = lane >> 4;
    int cl = w * 2 + half;
    int d = d0 + cl;
    int jlo = tid & 15;
    int tl_r = tid >> 4, cl_r = tid & 15;
    float Aval = -__expf(A_log[d * D_STATE + s]);
    float Dvj = Dp[d0 + jlo];
    float h = 0.f;

    for (int t0 = 0; t0 < TSEQ; t0 += 64) {
        for (int i = tid; i < 1024; i += 256) {
            int ti = i >> 4, j = i & 15;
            size_t row = (size_t)b * TSEQ + t0 + ti;
            sbc[i] = make_float2(g_xdbc[row * 96 + 64 + j],
                                 g_xdbc[row * 96 + 80 + j]);
            float dcv = __half2float(g_dch[row * D_INNER + d0 + j]);
            float xcv = __half2float(g_xch[row * D_INNER + d0 + j]);
            sdd[i] = make_float2(dcv, dcv * xcv);
            se[i]  = xcv * Dvj;
            float zv = g_xz[row * (2*D_INNER) + D_INNER + d0 + j];
            sg[i]  = zv / (1.f + __expf(-zv));
        }
        __syncthreads();
        #pragma unroll
        for (int sub = 0; sub < 4; sub++) {
            #pragma unroll
            for (int i = 0; i < 16; i++) {
                int t = sub * 16 + i;
                float2 dd = sdd[t*16 + cl];
                float2 bc = sbc[t*16 + s];
                float r = __expf(dd.x * Aval);
                h = fmaf(r, h, dd.y * bc.x);
                sP[(i*16 + cl)*20 + s] = h * bc.y;
            }
            __syncthreads();
            {
                int base = (tl_r*16 + cl_r)*20;
                float4 va = *(const float4*)&sP[base];
                float4 vb = *(const float4*)&sP[base+4];
                float4 vc = *(const float4*)&sP[base+8];
                float4 vd = *(const float4*)&sP[base+12];
                float p = va.x+va.y+va.z+va.w + vb.x+vb.y+vb.z+vb.w
                        + vc.x+vc.y+vc.z+vc.w + vd.x+vd.y+vd.z+vd.w;
                int t = sub * 16 + tl_r;
                float yv = (p + se[t*16 + cl_r]) * sg[t*16 + cl_r];
                size_t row = (size_t)b * TSEQ + t0 + t;
                g_yh[row * D_INNER + d0 + cl_r] = __float2half(yv);
            }
            __syncthreads();
        }
    }
}

// ---------------- launch ----------------
extern "C" void kernel_launch(void* const* d_in, const int* in_sizes, int n_in,
                              void* d_out, int out_size) {
    (void)in_sizes; (void)n_in; (void)out_size;
    const float* x          = (const float*)d_in[0];
    const float* in_proj_w  = (const float*)d_in[1];
    const float* conv_w     = (const float*)d_in[2];
    const float* conv_b     = (const float*)d_in[3];
    const float* x_proj_w   = (const float*)d_in[4];
    const float* dt_proj_w  = (const float*)d_in[5];
    const float* dt_proj_b  = (const float*)d_in[6];
    const float* A_log      = (const float*)d_in[7];
    const float* Dp         = (const float*)d_in[8];
    const float* out_proj_w = (const float*)d_in[9];
    const float* norm_w     = (const float*)d_in[10];
    float* out = (float*)d_out;

    fp16 *xnh, *inwh, *xpwh, *dtwh, *opwh, *xch, *dth, *yh, *dch;
    float *xz, *xpp;
    cudaGetSymbolAddress((void**)&xnh,  g_xnh);
    cudaGetSymbolAddress((void**)&inwh, g_inwh);
    cudaGetSymbolAddress((void**)&xpwh, g_xpwh);
    cudaGetSymbolAddress((void**)&dtwh, g_dtwh);
    cudaGetSymbolAddress((void**)&opwh, g_opwh);
    cudaGetSymbolAddress((void**)&xch,  g_xch);
    cudaGetSymbolAddress((void**)&dth,  g_dth);
    cudaGetSymbolAddress((void**)&yh,   g_yh);
    cudaGetSymbolAddress((void**)&dch,  g_dch);
    cudaGetSymbolAddress((void**)&xz,   g_xz);
    cudaGetSymbolAddress((void**)&xpp,  g_xpp);

    cudaFuncSetAttribute((const void*)gemm_mma<0>, cudaFuncAttributeMaxDynamicSharedMemorySize, GSMEM);
    cudaFuncSetAttribute((const void*)gemm_mma<1>, cudaFuncAttributeMaxDynamicSharedMemorySize, GSMEM);
    cudaFuncSetAttribute((const void*)gemm_mma<2>, cudaFuncAttributeMaxDynamicSharedMemorySize, GSMEM);
    cudaFuncSetAttribute((const void*)gemm_mma<4>, cudaFuncAttributeMaxDynamicSharedMemorySize, GSMEM);

    // 1. in_proj weight convert
    wprep_in<<<(C1 + 255)/256, 256>>>((const float4*)in_proj_w);
    // 2. other weight converts + rmsnorm (merged)
    wprep_rest_rms<<<CRB + MROWS, 256>>>((const float4*)out_proj_w,
                                         (const float4*)x_proj_w,
                                         (const float4*)dt_proj_w,
                                         x, norm_w);
    // 3. in_proj -> xz fp32
    gemm_mma<0><<<dim3(32, 32, 1), 256, GSMEM>>>(xnh, inwh,
        D_MODEL, 2*D_INNER, 2*D_INNER, xz, nullptr, nullptr);

    // 4. tiled conv + silu -> xch fp16  (profiler slot 4)
    conv_tiled<<<(MROWS/64) * 16, 256>>>(conv_w, conv_b);

    // 5. x_proj (1-term, split-K=8 -> partial buffers)
    gemm_mma<4><<<dim3(1, 32, XP_SPLIT), 256, GSMEM>>>(xch, xpwh,
        D_INNER, 96, 96, xpp, nullptr, nullptr);

    // 6. reduce partials -> xdbc + dt fp16
    xp_reduce_kernel<<<(MROWS*96 + 255)/256, 256>>>();

    // 7. dt_proj (1-term) + softplus/clip -> dc fp16
    gemm_mma<1><<<dim3(16, 32, 1), 256, GSMEM>>>(dth, dtwh,
        DT_RANK, D_INNER, D_INNER, nullptr, dt_proj_b, dch);

    // 8. selective scan
    scan_kernel<<<NB * (D_INNER/16), 256>>>(A_log, Dp);

    // 9. out_proj (1-term fp16) + residual
    gemm_mma<2><<<dim3(8, 32, 1), 256, GSMEM>>>(yh, opwh,
        D_INNER, D_MODEL, D_MODEL, out, x, nullptr);
}

// round 16
// speedup vs baseline: 1.2380x; 1.0936x over previous
#include <cuda_runtime.h>
#include <cuda_fp16.h>
#include <math.h>
#include <stdint.h>

#define D_MODEL 1024
#define D_INNER 2048
#define D_STATE 16
#define DT_RANK 64
#define NB 2
#define TSEQ 2048
#define MROWS (NB*TSEQ)   /* 4096 */
#define EPSV 1e-6f
#define XP_SPLIT 8

typedef __half fp16;

// ---------------- scratch (no allocations allowed) ----------------
__device__ fp16  g_xnh[MROWS*D_MODEL];
__device__ fp16  g_inwh[2*D_INNER*D_MODEL];
__device__ fp16  g_xpwh[96*D_INNER];
__device__ fp16  g_dtwh[D_INNER*DT_RANK];
__device__ fp16  g_opwh[D_MODEL*D_INNER];
__device__ float g_xzx[MROWS*D_INNER];          // x-half of in_proj, fp32
__device__ fp16  g_sgh[MROWS*D_INNER];          // silu(z), fp16
__device__ fp16  g_xch[MROWS*D_INNER];
__device__ float g_xpp[XP_SPLIT*MROWS*96];
__device__ float g_xdbc[MROWS*96];
__device__ fp16  g_dth[MROWS*DT_RANK];
__device__ fp16  g_dch[MROWS*D_INNER];
__device__ fp16  g_yh[MROWS*D_INNER];

// ---------------- helpers ----------------
__device__ __forceinline__ uint32_t s2u(const void* p) {
    uint32_t a;
    asm("{ .reg .u64 t; cvta.to.shared.u64 t, %1; cvt.u32.u64 %0, t; }" : "=r"(a) : "l"(p));
    return a;
}
__device__ __forceinline__ void cpa16(uint32_t dst, const void* src) {
    asm volatile("cp.async.cg.shared.global [%0], [%1], 16;" :: "r"(dst), "l"(src) : "memory");
}
__device__ __forceinline__ void cpa16z(uint32_t dst, const void* src, int sz) {
    asm volatile("cp.async.cg.shared.global [%0], [%1], 16, %2;" :: "r"(dst), "l"(src), "r"(sz) : "memory");
}
#define CPA_COMMIT() asm volatile("cp.async.commit_group;" ::: "memory")

#define LDSM4(r, a) \
    asm volatile("ldmatrix.sync.aligned.m8n8.x4.shared.b16 {%0,%1,%2,%3}, [%4];" \
        : "=r"((r)[0]),"=r"((r)[1]),"=r"((r)[2]),"=r"((r)[3]) : "r"(a))

#define MMA16816(d, a, b0, b1) \
    asm volatile("mma.sync.aligned.m16n8k16.row.col.f32.f16.f16.f32 " \
        "{%0,%1,%2,%3}, {%4,%5,%6,%7}, {%8,%9}, {%0,%1,%2,%3};" \
        : "+f"((d)[0]),"+f"((d)[1]),"+f"((d)[2]),"+f"((d)[3]) \
        : "r"((a)[0]),"r"((a)[1]),"r"((a)[2]),"r"((a)[3]), "r"(b0),"r"(b1))

// ---------------- fp16 GEMM via mma.sync (R8-proven full-chunk pipeline) ----------------
// EPI 0: x-half -> o0 fp32 (compact), z-half -> silu -> oh fp16
// EPI 1: dc=clip(softplus(v+bias)) -> fp16 oh   EPI 2: C=v+res   EPI 4: split-K partials
#define GSMEM (3 * 32768)
template<int EPI>
__global__ __launch_bounds__(256, 2)
void gemm_mma(const fp16* __restrict__ A, const fp16* __restrict__ B,
              int K, int Nreal, int ldc,
              float* __restrict__ o0,
              const float* __restrict__ e0,
              fp16* __restrict__ oh)
{
    extern __shared__ char dyn[];
    const uint32_t sbase = s2u(dyn);
    const int tid = threadIdx.x, lane = tid & 31, wid = tid >> 5;
    const int wm = wid >> 2, wn = wid & 3;
    const int m0 = blockIdx.y * 128, n0 = blockIdx.x * 128;
    const int NCtot = K / 64;
    const int per = (NCtot + gridDim.z - 1) / gridDim.z;
    const int kc0 = blockIdx.z * per;
    const int kc1 = min(NCtot, kc0 + per);

    float acc[4][4][4];
    #pragma unroll
    for (int i = 0; i < 4; i++)
        #pragma unroll
        for (int j = 0; j < 4; j++)
            #pragma unroll
            for (int k = 0; k < 4; k++) acc[i][j][k] = 0.f;

    auto load_stage = [&](int s, int kc) {
        int kk = kc * 64;
        uint32_t st = sbase + s * 32768;
        #pragma unroll
        for (int j = 0; j < 4; j++) {
            int idx = tid + j * 256;
            int r = idx >> 3, c = idx & 7;
            cpa16(st + r * 128 + ((c ^ (r & 7)) * 16),
                  A + (size_t)(m0 + r) * K + kk + c * 8);
        }
        uint32_t sb = st + 16384;
        #pragma unroll
        for (int j = 0; j < 4; j++) {
            int idx = tid + j * 256;
            int r = idx >> 3, c = idx & 7;
            int nr = n0 + r;
            int ok = nr < Nreal;
            cpa16z(sb + r * 128 + ((c ^ (r & 7)) * 16),
                   B + (size_t)(ok ? nr : 0) * K + kk + c * 8, ok ? 16 : 0);
        }
    };

    if (kc0 < kc1)     load_stage(0, kc0);
    CPA_COMMIT();
    if (kc0 + 1 < kc1) load_stage(1, kc0 + 1);
    CPA_COMMIT();

    for (int kc = kc0; kc < kc1; kc++) {
        int i = kc - kc0;
        int s = i % 3;
        asm volatile("cp.async.wait_group 1;" ::: "memory");
        __syncthreads();
        if (kc + 2 < kc1) load_stage((i + 2) % 3, kc + 2);
        CPA_COMMIT();

        uint32_t sA = sbase + s * 32768;
        uint32_t sB = sA + 16384;
        #pragma unroll
        for (int ks = 0; ks < 4; ks++) {
            uint32_t a[4][4], b[2][4];
            #pragma unroll
            for (int mi = 0; mi < 4; mi++) {
                int r = wm * 64 + mi * 16 + (lane & 15);
                int c = (2 * ks + (lane >> 4)) ^ (r & 7);
                LDSM4(a[mi], sA + r * 128 + c * 16);
            }
            #pragma unroll
            for (int g = 0; g < 2; g++) {
                int r = wn * 32 + g * 16 + (lane & 7) + ((lane >> 4) & 1) * 8;
                int c = (2 * ks + ((lane >> 3) & 1)) ^ (r & 7);
                LDSM4(b[g], sB + r * 128 + c * 16);
            }
            #pragma unroll
            for (int mi = 0; mi < 4; mi++)
                #pragma unroll
                for (int nj = 0; nj < 4; nj++) {
                    int bg = nj >> 1, br = (nj & 1) * 2;
                    MMA16816(acc[mi][nj], a[mi], b[bg][br], b[bg][br+1]);
                }
        }
    }

    #pragma unroll
    for (int mi = 0; mi < 4; mi++)
        #pragma unroll
        for (int nj = 0; nj < 4; nj++)
            #pragma unroll
            for (int h = 0; h < 2; h++) {
                int m = m0 + wm*64 + mi*16 + (lane >> 2) + h*8;
                int nb = n0 + wn*32 + nj*8 + (lane & 3)*2;
                float vx = acc[mi][nj][h*2], vy = acc[mi][nj][h*2+1];
                size_t ci = (size_t)m * ldc + nb;
                if (EPI == 0) {
                    if (nb < D_INNER) {
                        *(float2*)(o0 + (size_t)m * D_INNER + nb) = make_float2(vx, vy);
                    } else {
                        float sx_ = vx / (1.f + __expf(-vx));
                        float sy_ = vy / (1.f + __expf(-vy));
                        __half2 hv; hv.x = __float2half(sx_); hv.y = __float2half(sy_);
                        *(__half2*)(oh + (size_t)m * D_INNER + nb - D_INNER) = hv;
                    }
                } else if (EPI == 1) {
                    vx += e0[nb]; vy += e0[nb+1];
                    float spx = (vx > 20.f) ? vx : log1pf(__expf(vx));
                    float spy = (vy > 20.f) ? vy : log1pf(__expf(vy));
                    float dx = fminf(fmaxf(spx, -10.f), 1.f);
                    float dy = fminf(fmaxf(spy, -10.f), 1.f);
                    __half2 hv; hv.x = __float2half(dx); hv.y = __float2half(dy);
                    *(__half2*)(oh + ci) = hv;
                } else if (EPI == 2) {
                    float2 rv = *(const float2*)(e0 + ci);
                    *(float2*)(o0 + ci) = make_float2(vx + rv.x, vy + rv.y);
                } else {
                    if (nb < Nreal) {
                        *(float2*)(o0 + (size_t)blockIdx.z * MROWS * 96
                                      + (size_t)m * 96 + nb) = make_float2(vx, vy);
                    }
                }
            }
}

// ---------------- weight prep (3 launches so in_proj lands in profiler slot 4) ----------------
#define C1 (2*D_INNER*D_MODEL/4)
#define CR ((D_MODEL*D_INNER + 96*D_INNER + D_INNER*DT_RANK)/4)
__global__ void wprep_in(const float4* __restrict__ w_in) {
    int i = blockIdx.x * 256 + threadIdx.x;
    if (i >= C1) return;
    float4 v = w_in[i];
    __half2 p0, p1;
    p0.x = __float2half(v.x); p0.y = __float2half(v.y);
    p1.x = __float2half(v.z); p1.y = __float2half(v.w);
    *(__half2*)(g_inwh + (size_t)i * 4)     = p0;
    *(__half2*)(g_inwh + (size_t)i * 4 + 2) = p1;
}
__global__ void wprep_rest(const float4* __restrict__ w_op,
                           const float4* __restrict__ w_xp,
                           const float4* __restrict__ w_dt) {
    int i = blockIdx.x * 256 + threadIdx.x;
    if (i >= CR) return;
    const float4* src;
    fp16* hi;
    int j = i;
    const int R1 = D_MODEL*D_INNER/4, R2 = R1 + 96*D_INNER/4;
    if (i < R1)      { src = w_op; hi = g_opwh; }
    else if (i < R2) { src = w_xp; hi = g_xpwh; j = i - R1; }
    else             { src = w_dt; hi = g_dtwh; j = i - R2; }
    float4 v = src[j];
    __half2 p0, p1;
    p0.x = __float2half(v.x); p0.y = __float2half(v.y);
    p1.x = __float2half(v.z); p1.y = __float2half(v.w);
    *(__half2*)(hi + (size_t)j * 4)     = p0;
    *(__half2*)(hi + (size_t)j * 4 + 2) = p1;
}

// ---------------- rmsnorm ----------------
__global__ void rmsnorm_kernel(const float* __restrict__ x,
                               const float* __restrict__ w) {
    __shared__ float red[8];
    __shared__ float sscale;
    int row = blockIdx.x;
    int tid = threadIdx.x;
    const float4* xr = (const float4*)(x + (size_t)row * D_MODEL);
    float4 v = xr[tid];
    float ss = v.x*v.x + v.y*v.y + v.z*v.z + v.w*v.w;
    #pragma unroll
    for (int off = 16; off > 0; off >>= 1)
        ss += __shfl_xor_sync(0xffffffffu, ss, off);
    int lane = tid & 31, wq = tid >> 5;
    if (lane == 0) red[wq] = ss;
    __syncthreads();
    if (tid == 0) {
        float t = 0.f;
        #pragma unroll
        for (int i2 = 0; i2 < 8; i2++) t += red[i2];
        sscale = rsqrtf(t * (1.0f / D_MODEL) + EPSV);
    }
    __syncthreads();
    float sc = sscale;
    float4 wv = ((const float4*)w)[tid];
    float o0 = v.x*sc*wv.x, o1 = v.y*sc*wv.y, o2 = v.z*sc*wv.z, o3 = v.w*sc*wv.w;
    size_t base = (size_t)row * D_MODEL + tid * 4;
    __half2 ph0, ph1;
    ph0.x = __float2half(o0); ph0.y = __float2half(o1);
    ph1.x = __float2half(o2); ph1.y = __float2half(o3);
    *(__half2*)(g_xnh+base)   = ph0; *(__half2*)(g_xnh+base+2) = ph1;
}

// ---------------- tiled depthwise causal conv(4) + silu -> fp16 ----------------
__global__ __launch_bounds__(256) void conv_tiled(const float* __restrict__ cw,
                                                  const float* __restrict__ cb) {
    __shared__ float sx[67*128];
    int db = blockIdx.x & 15, tb = blockIdx.x >> 4;
    int t0 = tb * 64;
    int d0 = db * 128;
    int tid = threadIdx.x;
    int tinb = t0 & (TSEQ - 1);
    for (int idx = tid; idx < 67*32; idx += 256) {
        int r = idx >> 5, c = idx & 31;
        int tloc = tinb - 3 + r;
        float4 v = make_float4(0.f, 0.f, 0.f, 0.f);
        if (tloc >= 0 && tloc < TSEQ)
            v = *(const float4*)(g_xzx + (size_t)(t0 - 3 + r) * D_INNER + d0 + c*4);
        *(float4*)&sx[r*128 + c*4] = v;
    }
    __syncthreads();
    int j = tid & 31;
    int i0 = (tid >> 5) * 8;
    int d = d0 + j*4;
    float wv[4][4];
    *(float4*)wv[0] = *(const float4*)(cw + (d+0)*4);
    *(float4*)wv[1] = *(const float4*)(cw + (d+1)*4);
    *(float4*)wv[2] = *(const float4*)(cw + (d+2)*4);
    *(float4*)wv[3] = *(const float4*)(cw + (d+3)*4);
    float4 bvv = *(const float4*)(cb + d);
    #pragma unroll
    for (int rep = 0; rep < 8; rep++) {
        int i = i0 + rep;
        float a0 = bvv.x, a1 = bvv.y, a2 = bvv.z, a3 = bvv.w;
        #pragma unroll
        for (int k = 0; k < 4; k++) {
            float4 xv = *(float4*)&sx[(i+k)*128 + j*4];
            a0 = fmaf(wv[0][k], xv.x, a0);
            a1 = fmaf(wv[1][k], xv.y, a1);
            a2 = fmaf(wv[2][k], xv.z, a2);
            a3 = fmaf(wv[3][k], xv.w, a3);
        }
        float o0 = a0/(1.f+__expf(-a0)), o1 = a1/(1.f+__expf(-a1));
        float o2 = a2/(1.f+__expf(-a2)), o3 = a3/(1.f+__expf(-a3));
        __half2 hv[2];
        hv[0].x = __float2half(o0); hv[0].y = __float2half(o1);
        hv[1].x = __float2half(o2); hv[1].y = __float2half(o3);
        *(uint2*)(g_xch + (size_t)(t0 + i) * D_INNER + d) = *(uint2*)hv;
    }
}

// ---------------- x_proj partial reduce + dt fp16 ----------------
__global__ void xp_reduce_kernel() {
    int i = blockIdx.x * 256 + threadIdx.x;
    if (i >= MROWS * 96) return;
    float s = 0.f;
    #pragma unroll
    for (int z = 0; z < XP_SPLIT; z++)
        s += g_xpp[(size_t)z * MROWS * 96 + i];
    g_xdbc[i] = s;
    int m = i / 96, n = i - m * 96;
    if (n < 64) g_dth[m*64 + n] = __float2half(s);
}

// ---------------- selective scan: reg-hoisted serial phase, fp16 gate ----------------
__global__ __launch_bounds__(256) void scan_kernel(const float* __restrict__ A_log,
                                                   const float* __restrict__ Dp) {
    __shared__ float2 sbc[64*16], sdd[64*16];
    __shared__ float se[64*16], sg[64*16];
    __shared__ float sP[16*16*20];
    int bid = blockIdx.x;
    int b = bid >> 7;
    int d0 = (bid & 127) << 4;
    int tid = threadIdx.x;
    int w = tid >> 5, lane = tid & 31;
    int s = lane & 15, half = lane >> 4;
    int cl = w * 2 + half;
    int d = d0 + cl;
    int jlo = tid & 15;
    int tl_r = tid >> 4, cl_r = tid & 15;
    float AvalL2 = -__expf(A_log[d * D_STATE + s]) * 1.44269504f;
    float Dvj = Dp[d0 + jlo];
    float h = 0.f;

    for (int t0 = 0; t0 < TSEQ; t0 += 64) {
        for (int i = tid; i < 1024; i += 256) {
            int ti = i >> 4, j = i & 15;
            size_t row = (size_t)b * TSEQ + t0 + ti;
            sbc[i] = make_float2(g_xdbc[row * 96 + 64 + j],
                                 g_xdbc[row * 96 + 80 + j]);
            float dcv = __half2float(g_dch[row * D_INNER + d0 + j]);
            float xcv = __half2float(g_xch[row * D_INNER + d0 + j]);
            sdd[i] = make_float2(dcv, dcv * xcv);
            se[i]  = xcv * Dvj;
            sg[i]  = __half2float(g_sgh[row * D_INNER + d0 + j]);
        }
        __syncthreads();
        #pragma unroll
        for (int sub = 0; sub < 4; sub++) {
            float2 ddv[16], bcv[16];
            #pragma unroll
            for (int i = 0; i < 16; i++) {
                int t = sub * 16 + i;
                ddv[i] = sdd[t*16 + cl];
                bcv[i] = sbc[t*16 + s];
            }
            #pragma unroll
            for (int i = 0; i < 16; i++) {
                float r = exp2f(ddv[i].x * AvalL2);
                h = fmaf(r, h, ddv[i].y * bcv[i].x);
                sP[(i*16 + cl)*20 + s] = h * bcv[i].y;
            }
            __syncthreads();
            {
                int base = (tl_r*16 + cl_r)*20;
                float4 va = *(const float4*)&sP[base];
                float4 vb = *(const float4*)&sP[base+4];
                float4 vc = *(const float4*)&sP[base+8];
                float4 vd = *(const float4*)&sP[base+12];
                float p = va.x+va.y+va.z+va.w + vb.x+vb.y+vb.z+vb.w
                        + vc.x+vc.y+vc.z+vc.w + vd.x+vd.y+vd.z+vd.w;
                int t = sub * 16 + tl_r;
                float yv = (p + se[t*16 + cl_r]) * sg[t*16 + cl_r];
                size_t row = (size_t)b * TSEQ + t0 + t;
                g_yh[row * D_INNER + d0 + cl_r] = __float2half(yv);
            }
            __syncthreads();
        }
    }
}

// ---------------- launch ----------------
extern "C" void kernel_launch(void* const* d_in, const int* in_sizes, int n_in,
                              void* d_out, int out_size) {
    (void)in_sizes; (void)n_in; (void)out_size;
    const float* x          = (const float*)d_in[0];
    const float* in_proj_w  = (const float*)d_in[1];
    const float* conv_w     = (const float*)d_in[2];
    const float* conv_b     = (const float*)d_in[3];
    const float* x_proj_w   = (const float*)d_in[4];
    const float* dt_proj_w  = (const float*)d_in[5];
    const float* dt_proj_b  = (const float*)d_in[6];
    const float* A_log      = (const float*)d_in[7];
    const float* Dp         = (const float*)d_in[8];
    const float* out_proj_w = (const float*)d_in[9];
    const float* norm_w     = (const float*)d_in[10];
    float* out = (float*)d_out;

    fp16 *xnh, *inwh, *xpwh, *dtwh, *opwh, *xch, *dth, *yh, *dch, *sgh;
    float *xzx, *xpp;
    cudaGetSymbolAddress((void**)&xnh,  g_xnh);
    cudaGetSymbolAddress((void**)&inwh, g_inwh);
    cudaGetSymbolAddress((void**)&xpwh, g_xpwh);
    cudaGetSymbolAddress((void**)&dtwh, g_dtwh);
    cudaGetSymbolAddress((void**)&opwh, g_opwh);
    cudaGetSymbolAddress((void**)&xch,  g_xch);
    cudaGetSymbolAddress((void**)&dth,  g_dth);
    cudaGetSymbolAddress((void**)&yh,   g_yh);
    cudaGetSymbolAddress((void**)&dch,  g_dch);
    cudaGetSymbolAddress((void**)&sgh,  g_sgh);
    cudaGetSymbolAddress((void**)&xzx,  g_xzx);
    cudaGetSymbolAddress((void**)&xpp,  g_xpp);

    cudaFuncSetAttribute((const void*)gemm_mma<0>, cudaFuncAttributeMaxDynamicSharedMemorySize, GSMEM);
    cudaFuncSetAttribute((const void*)gemm_mma<1>, cudaFuncAttributeMaxDynamicSharedMemorySize, GSMEM);
    cudaFuncSetAttribute((const void*)gemm_mma<2>, cudaFuncAttributeMaxDynamicSharedMemorySize, GSMEM);
    cudaFuncSetAttribute((const void*)gemm_mma<4>, cudaFuncAttributeMaxDynamicSharedMemorySize, GSMEM);

    // 1-3. weight prep + rmsnorm
    wprep_in<<<(C1 + 255)/256, 256>>>((const float4*)in_proj_w);
    wprep_rest<<<(CR + 255)/256, 256>>>((const float4*)out_proj_w,
                                        (const float4*)x_proj_w,
                                        (const float4*)dt_proj_w);
    rmsnorm_kernel<<<MROWS, 256>>>(x, norm_w);

    // 4. in_proj (profiler slot 4): x-half -> xzx fp32, z-half -> silu fp16
    gemm_mma<0><<<dim3(32, 32, 1), 256, GSMEM>>>(xnh, inwh,
        D_MODEL, 2*D_INNER, 2*D_INNER, xzx, nullptr, sgh);

    // 5. tiled conv + silu -> xch fp16
    conv_tiled<<<(MROWS/64) * 16, 256>>>(conv_w, conv_b);

    // 6. x_proj (1-term, split-K=8 -> partial buffers)
    gemm_mma<4><<<dim3(1, 32, XP_SPLIT), 256, GSMEM>>>(xch, xpwh,
        D_INNER, 96, 96, xpp, nullptr, nullptr);

    // 7. reduce partials -> xdbc + dt fp16
    xp_reduce_kernel<<<(MROWS*96 + 255)/256, 256>>>();

    // 8. dt_proj (1-term) + softplus/clip -> dc fp16
    gemm_mma<1><<<dim3(16, 32, 1), 256, GSMEM>>>(dth, dtwh,
        DT_RANK, D_INNER, D_INNER, nullptr, dt_proj_b, dch);

    // 9. selective scan
    scan_kernel<<<NB * (D_INNER/16), 256>>>(A_log, Dp);

    // 10. out_proj (1-term fp16) + residual
    gemm_mma<2><<<dim3(8, 32, 1), 256, GSMEM>>>(yh, opwh,
        D_INNER, D_MODEL, D_MODEL, out, x, nullptr);
}

// round 17
// speedup vs baseline: 1.3882x; 1.1214x over previous
#include <cuda_runtime.h>
#include <cuda_fp16.h>
#include <math.h>
#include <stdint.h>

#define D_MODEL 1024
#define D_INNER 2048
#define D_STATE 16
#define DT_RANK 64
#define NB 2
#define TSEQ 2048
#define MROWS (NB*TSEQ)   /* 4096 */
#define EPSV 1e-6f
#define XP_SPLIT 8

typedef __half fp16;

// ---------------- scratch (no allocations allowed) ----------------
__device__ fp16  g_xnh[MROWS*D_MODEL];
__device__ fp16  g_inwh[2*D_INNER*D_MODEL];
__device__ fp16  g_xpwh[96*D_INNER];
__device__ fp16  g_dtwh[D_INNER*DT_RANK];
__device__ fp16  g_opwh[D_MODEL*D_INNER];
__device__ float g_xzx[MROWS*D_INNER];
__device__ fp16  g_sgh[MROWS*D_INNER];
__device__ fp16  g_xch[MROWS*D_INNER];
__device__ float g_xpp[XP_SPLIT*MROWS*96];
__device__ float g_xdbc[MROWS*96];
__device__ fp16  g_dth[MROWS*DT_RANK];
__device__ fp16  g_dch[MROWS*D_INNER];
__device__ fp16  g_yh[MROWS*D_INNER];

// ---------------- helpers ----------------
__device__ __forceinline__ uint32_t s2u(const void* p) {
    uint32_t a;
    asm("{ .reg .u64 t; cvta.to.shared.u64 t, %1; cvt.u32.u64 %0, t; }" : "=r"(a) : "l"(p));
    return a;
}
__device__ __forceinline__ void cpa16(uint32_t dst, const void* src) {
    asm volatile("cp.async.cg.shared.global [%0], [%1], 16;" :: "r"(dst), "l"(src) : "memory");
}
__device__ __forceinline__ void cpa16z(uint32_t dst, const void* src, int sz) {
    asm volatile("cp.async.cg.shared.global [%0], [%1], 16, %2;" :: "r"(dst), "l"(src), "r"(sz) : "memory");
}
#define CPA_COMMIT() asm volatile("cp.async.commit_group;" ::: "memory")

#define LDSM4(r, a) \
    asm volatile("ldmatrix.sync.aligned.m8n8.x4.shared.b16 {%0,%1,%2,%3}, [%4];" \
        : "=r"((r)[0]),"=r"((r)[1]),"=r"((r)[2]),"=r"((r)[3]) : "r"(a))

#define MMA16816(d, a, b0, b1) \
    asm volatile("mma.sync.aligned.m16n8k16.row.col.f32.f16.f16.f32 " \
        "{%0,%1,%2,%3}, {%4,%5,%6,%7}, {%8,%9}, {%0,%1,%2,%3};" \
        : "+f"((d)[0]),"+f"((d)[1]),"+f"((d)[2]),"+f"((d)[3]) \
        : "r"((a)[0]),"r"((a)[1]),"r"((a)[2]),"r"((a)[3]), "r"(b0),"r"(b1))

// ---------------- fp16 GEMM via mma.sync (R8-proven full-chunk pipeline) ----------------
#define GSMEM (3 * 32768)
template<int EPI>
__global__ __launch_bounds__(256, 2)
void gemm_mma(const fp16* __restrict__ A, const fp16* __restrict__ B,
              int K, int Nreal, int ldc,
              float* __restrict__ o0,
              const float* __restrict__ e0,
              fp16* __restrict__ oh)
{
    extern __shared__ char dyn[];
    const uint32_t sbase = s2u(dyn);
    const int tid = threadIdx.x, lane = tid & 31, wid = tid >> 5;
    const int wm = wid >> 2, wn = wid & 3;
    const int m0 = blockIdx.y * 128, n0 = blockIdx.x * 128;
    const int NCtot = K / 64;
    const int per = (NCtot + gridDim.z - 1) / gridDim.z;
    const int kc0 = blockIdx.z * per;
    const int kc1 = min(NCtot, kc0 + per);

    float acc[4][4][4];
    #pragma unroll
    for (int i = 0; i < 4; i++)
        #pragma unroll
        for (int j = 0; j < 4; j++)
            #pragma unroll
            for (int k = 0; k < 4; k++) acc[i][j][k] = 0.f;

    auto load_stage = [&](int s, int kc) {
        int kk = kc * 64;
        uint32_t st = sbase + s * 32768;
        #pragma unroll
        for (int j = 0; j < 4; j++) {
            int idx = tid + j * 256;
            int r = idx >> 3, c = idx & 7;
            cpa16(st + r * 128 + ((c ^ (r & 7)) * 16),
                  A + (size_t)(m0 + r) * K + kk + c * 8);
        }
        uint32_t sb = st + 16384;
        #pragma unroll
        for (int j = 0; j < 4; j++) {
            int idx = tid + j * 256;
            int r = idx >> 3, c = idx & 7;
            int nr = n0 + r;
            int ok = nr < Nreal;
            cpa16z(sb + r * 128 + ((c ^ (r & 7)) * 16),
                   B + (size_t)(ok ? nr : 0) * K + kk + c * 8, ok ? 16 : 0);
        }
    };

    if (kc0 < kc1)     load_stage(0, kc0);
    CPA_COMMIT();
    if (kc0 + 1 < kc1) load_stage(1, kc0 + 1);
    CPA_COMMIT();

    for (int kc = kc0; kc < kc1; kc++) {
        int i = kc - kc0;
        int s = i % 3;
        asm volatile("cp.async.wait_group 1;" ::: "memory");
        __syncthreads();
        if (kc + 2 < kc1) load_stage((i + 2) % 3, kc + 2);
        CPA_COMMIT();

        uint32_t sA = sbase + s * 32768;
        uint32_t sB = sA + 16384;
        #pragma unroll
        for (int ks = 0; ks < 4; ks++) {
            uint32_t a[4][4], b[2][4];
            #pragma unroll
            for (int mi = 0; mi < 4; mi++) {
                int r = wm * 64 + mi * 16 + (lane & 15);
                int c = (2 * ks + (lane >> 4)) ^ (r & 7);
                LDSM4(a[mi], sA + r * 128 + c * 16);
            }
            #pragma unroll
            for (int g = 0; g < 2; g++) {
                int r = wn * 32 + g * 16 + (lane & 7) + ((lane >> 4) & 1) * 8;
                int c = (2 * ks + ((lane >> 3) & 1)) ^ (r & 7);
                LDSM4(b[g], sB + r * 128 + c * 16);
            }
            #pragma unroll
            for (int mi = 0; mi < 4; mi++)
                #pragma unroll
                for (int nj = 0; nj < 4; nj++) {
                    int bg = nj >> 1, br = (nj & 1) * 2;
                    MMA16816(acc[mi][nj], a[mi], b[bg][br], b[bg][br+1]);
                }
        }
    }

    #pragma unroll
    for (int mi = 0; mi < 4; mi++)
        #pragma unroll
        for (int nj = 0; nj < 4; nj++)
            #pragma unroll
            for (int h = 0; h < 2; h++) {
                int m = m0 + wm*64 + mi*16 + (lane >> 2) + h*8;
                int nb = n0 + wn*32 + nj*8 + (lane & 3)*2;
                float vx = acc[mi][nj][h*2], vy = acc[mi][nj][h*2+1];
                size_t ci = (size_t)m * ldc + nb;
                if (EPI == 0) {
                    if (nb < D_INNER) {
                        *(float2*)(o0 + (size_t)m * D_INNER + nb) = make_float2(vx, vy);
                    } else {
                        float sx_ = vx / (1.f + __expf(-vx));
                        float sy_ = vy / (1.f + __expf(-vy));
                        __half2 hv; hv.x = __float2half(sx_); hv.y = __float2half(sy_);
                        *(__half2*)(oh + (size_t)m * D_INNER + nb - D_INNER) = hv;
                    }
                } else if (EPI == 1) {
                    vx += e0[nb]; vy += e0[nb+1];
                    float spx = fmaxf(vx, 0.f) + __logf(1.f + __expf(-fabsf(vx)));
                    float spy = fmaxf(vy, 0.f) + __logf(1.f + __expf(-fabsf(vy)));
                    float dx = fminf(fmaxf(spx, -10.f), 1.f);
                    float dy = fminf(fmaxf(spy, -10.f), 1.f);
                    __half2 hv; hv.x = __float2half(dx); hv.y = __float2half(dy);
                    *(__half2*)(oh + ci) = hv;
                } else if (EPI == 2) {
                    float2 rv = *(const float2*)(e0 + ci);
                    *(float2*)(o0 + ci) = make_float2(vx + rv.x, vy + rv.y);
                } else {
                    if (nb < Nreal) {
                        *(float2*)(o0 + (size_t)blockIdx.z * MROWS * 96
                                      + (size_t)m * 96 + nb) = make_float2(vx, vy);
                    }
                }
            }
}

// ---------------- weight prep ----------------
#define C1 (2*D_INNER*D_MODEL/4)
#define CR ((D_MODEL*D_INNER + 96*D_INNER + D_INNER*DT_RANK)/4)
__global__ void wprep_in(const float4* __restrict__ w_in) {
    int i = blockIdx.x * 256 + threadIdx.x;
    if (i >= C1) return;
    float4 v = w_in[i];
    __half2 p0, p1;
    p0.x = __float2half(v.x); p0.y = __float2half(v.y);
    p1.x = __float2half(v.z); p1.y = __float2half(v.w);
    *(__half2*)(g_inwh + (size_t)i * 4)     = p0;
    *(__half2*)(g_inwh + (size_t)i * 4 + 2) = p1;
}
__global__ void wprep_rest(const float4* __restrict__ w_op,
                           const float4* __restrict__ w_xp,
                           const float4* __restrict__ w_dt) {
    int i = blockIdx.x * 256 + threadIdx.x;
    if (i >= CR) return;
    const float4* src;
    fp16* hi;
    int j = i;
    const int R1 = D_MODEL*D_INNER/4, R2 = R1 + 96*D_INNER/4;
    if (i < R1)      { src = w_op; hi = g_opwh; }
    else if (i < R2) { src = w_xp; hi = g_xpwh; j = i - R1; }
    else             { src = w_dt; hi = g_dtwh; j = i - R2; }
    float4 v = src[j];
    __half2 p0, p1;
    p0.x = __float2half(v.x); p0.y = __float2half(v.y);
    p1.x = __float2half(v.z); p1.y = __float2half(v.w);
    *(__half2*)(hi + (size_t)j * 4)     = p0;
    *(__half2*)(hi + (size_t)j * 4 + 2) = p1;
}

// ---------------- rmsnorm ----------------
__global__ void rmsnorm_kernel(const float* __restrict__ x,
                               const float* __restrict__ w) {
    __shared__ float red[8];
    __shared__ float sscale;
    int row = blockIdx.x;
    int tid = threadIdx.x;
    const float4* xr = (const float4*)(x + (size_t)row * D_MODEL);
    float4 v = xr[tid];
    float ss = v.x*v.x + v.y*v.y + v.z*v.z + v.w*v.w;
    #pragma unroll
    for (int off = 16; off > 0; off >>= 1)
        ss += __shfl_xor_sync(0xffffffffu, ss, off);
    int lane = tid & 31, wq = tid >> 5;
    if (lane == 0) red[wq] = ss;
    __syncthreads();
    if (tid == 0) {
        float t = 0.f;
        #pragma unroll
        for (int i2 = 0; i2 < 8; i2++) t += red[i2];
        sscale = rsqrtf(t * (1.0f / D_MODEL) + EPSV);
    }
    __syncthreads();
    float sc = sscale;
    float4 wv = ((const float4*)w)[tid];
    float o0 = v.x*sc*wv.x, o1 = v.y*sc*wv.y, o2 = v.z*sc*wv.z, o3 = v.w*sc*wv.w;
    size_t base = (size_t)row * D_MODEL + tid * 4;
    __half2 ph0, ph1;
    ph0.x = __float2half(o0); ph0.y = __float2half(o1);
    ph1.x = __float2half(o2); ph1.y = __float2half(o3);
    *(__half2*)(g_xnh+base)   = ph0; *(__half2*)(g_xnh+base+2) = ph1;
}

// ---------------- tiled depthwise causal conv(4) + silu -> fp16 ----------------
__global__ __launch_bounds__(256) void conv_tiled(const float* __restrict__ cw,
                                                  const float* __restrict__ cb) {
    __shared__ float sx[67*128];
    int db = blockIdx.x & 15, tb = blockIdx.x >> 4;
    int t0 = tb * 64;
    int d0 = db * 128;
    int tid = threadIdx.x;
    int tinb = t0 & (TSEQ - 1);
    for (int idx = tid; idx < 67*32; idx += 256) {
        int r = idx >> 5, c = idx & 31;
        int tloc = tinb - 3 + r;
        float4 v = make_float4(0.f, 0.f, 0.f, 0.f);
        if (tloc >= 0 && tloc < TSEQ)
            v = *(const float4*)(g_xzx + (size_t)(t0 - 3 + r) * D_INNER + d0 + c*4);
        *(float4*)&sx[r*128 + c*4] = v;
    }
    __syncthreads();
    int j = tid & 31;
    int i0 = (tid >> 5) * 8;
    int d = d0 + j*4;
    float wv[4][4];
    *(float4*)wv[0] = *(const float4*)(cw + (d+0)*4);
    *(float4*)wv[1] = *(const float4*)(cw + (d+1)*4);
    *(float4*)wv[2] = *(const float4*)(cw + (d+2)*4);
    *(float4*)wv[3] = *(const float4*)(cw + (d+3)*4);
    float4 bvv = *(const float4*)(cb + d);
    #pragma unroll
    for (int rep = 0; rep < 8; rep++) {
        int i = i0 + rep;
        float a0 = bvv.x, a1 = bvv.y, a2 = bvv.z, a3 = bvv.w;
        #pragma unroll
        for (int k = 0; k < 4; k++) {
            float4 xv = *(float4*)&sx[(i+k)*128 + j*4];
            a0 = fmaf(wv[0][k], xv.x, a0);
            a1 = fmaf(wv[1][k], xv.y, a1);
            a2 = fmaf(wv[2][k], xv.z, a2);
            a3 = fmaf(wv[3][k], xv.w, a3);
        }
        float o0 = a0/(1.f+__expf(-a0)), o1 = a1/(1.f+__expf(-a1));
        float o2 = a2/(1.f+__expf(-a2)), o3 = a3/(1.f+__expf(-a3));
        __half2 hv[2];
        hv[0].x = __float2half(o0); hv[0].y = __float2half(o1);
        hv[1].x = __float2half(o2); hv[1].y = __float2half(o3);
        *(uint2*)(g_xch + (size_t)(t0 + i) * D_INNER + d) = *(uint2*)hv;
    }
}

// ---------------- x_proj partial reduce + dt fp16 ----------------
__global__ void xp_reduce_kernel() {
    int i = blockIdx.x * 256 + threadIdx.x;
    if (i >= MROWS * 96) return;
    float s = 0.f;
    #pragma unroll
    for (int z = 0; z < XP_SPLIT; z++)
        s += g_xpp[(size_t)z * MROWS * 96 + i];
    g_xdbc[i] = s;
    int m = i / 96, n = i - m * 96;
    if (n < 64) g_dth[m*64 + n] = __float2half(s);
}

// ---------------- selective scan: cp.async double-buffered staging ----------------
// dyn smem layout (bytes):
//   raw buf b (b=0,1) at b*14336: rB f32[1024] | rC f32[1024]@+4096 |
//     rdc fp16[1024]@+8192 | rxc @+10240 | rsg @+12288
//   staged @28672: sdd float2[1024] | sbc float2[1024]@+8192 | se f32[1024]@+16384 | sg f32[1024]@+20480
//   sP @53248: f32[16*16*20]
#define SCAN_SMEM 78848
__global__ __launch_bounds__(256) void scan_kernel(const float* __restrict__ A_log,
                                                   const float* __restrict__ Dp) {
    extern __shared__ char dyn[];
    const uint32_t sbase = s2u(dyn);
    float2* sdd = (float2*)(dyn + 28672);
    float2* sbc = (float2*)(dyn + 36864);
    float*  sep = (float*)(dyn + 45056);
    float*  sgp = (float*)(dyn + 49152);
    float*  sP  = (float*)(dyn + 53248);
    int bid = blockIdx.x;
    int bq = bid >> 7;
    int d0 = (bid & 127) << 4;
    int tid = threadIdx.x;
    int w = tid >> 5, lane = tid & 31;
    int s = lane & 15, half = lane >> 4;
    int cl = w * 2 + half;
    int d = d0 + cl;
    int tl_r = tid >> 4, cl_r = tid & 15;
    float AvalL2 = -__expf(A_log[d * D_STATE + s]) * 1.44269504f;
    float Dvj = Dp[d0 + (tid & 15)];

    auto prefetch = [&](int b, int t0) {
        uint32_t rbase = sbase + b * 14336;
        int r = tid >> 2, c = tid & 3;
        size_t grow = (size_t)bq * TSEQ + t0 + r;
        cpa16(rbase + tid * 16,        g_xdbc + grow * 96 + 64 + c * 4);
        cpa16(rbase + 4096 + tid * 16, g_xdbc + grow * 96 + 80 + c * 4);
        if (tid < 128) {
            int r2 = tid >> 1, c2 = tid & 1;
            size_t goff = ((size_t)bq * TSEQ + t0 + r2) * D_INNER + d0 + c2 * 8;
            cpa16(rbase + 8192  + tid * 16, g_dch + goff);
            cpa16(rbase + 10240 + tid * 16, g_xch + goff);
            cpa16(rbase + 12288 + tid * 16, g_sgh + goff);
        }
    };

    float h = 0.f;
    prefetch(0, 0);
    CPA_COMMIT();

    for (int cb = 0; cb < 32; cb++) {
        int t0 = cb * 64;
        asm volatile("cp.async.wait_group 0;" ::: "memory");
        __syncthreads();
        // convert raw -> staged (pure smem)
        {
            const float* rBf = (const float*)(dyn + (cb & 1) * 14336);
            const float* rCf = rBf + 1024;
            const fp16* rdc = (const fp16*)(dyn + (cb & 1) * 14336 + 8192);
            const fp16* rxc = (const fp16*)(dyn + (cb & 1) * 14336 + 10240);
            const fp16* rsg = (const fp16*)(dyn + (cb & 1) * 14336 + 12288);
            #pragma unroll
            for (int k = 0; k < 4; k++) {
                int i = tid + k * 256;
                float dcv = __half2float(rdc[i]);
                float xcv = __half2float(rxc[i]);
                sbc[i] = make_float2(rBf[i], rCf[i]);
                sdd[i] = make_float2(dcv, dcv * xcv);
                sep[i] = xcv * Dvj;
                sgp[i] = __half2float(rsg[i]);
            }
        }
        __syncthreads();
        if (cb + 1 < 32) { prefetch((cb + 1) & 1, t0 + 64); }
        CPA_COMMIT();

        #pragma unroll
        for (int sub = 0; sub < 4; sub++) {
            float2 ddv[16], bcv[16];
            #pragma unroll
            for (int i = 0; i < 16; i++) {
                int t = sub * 16 + i;
                ddv[i] = sdd[t*16 + cl];
                bcv[i] = sbc[t*16 + s];
            }
            #pragma unroll
            for (int i = 0; i < 16; i++) {
                float r = exp2f(ddv[i].x * AvalL2);
                h = fmaf(r, h, ddv[i].y * bcv[i].x);
                sP[(i*16 + cl)*20 + s] = h * bcv[i].y;
            }
            __syncthreads();
            {
                int base = (tl_r*16 + cl_r)*20;
                float4 va = *(const float4*)&sP[base];
                float4 vb = *(const float4*)&sP[base+4];
                float4 vc = *(const float4*)&sP[base+8];
                float4 vd = *(const float4*)&sP[base+12];
                float p = va.x+va.y+va.z+va.w + vb.x+vb.y+vb.z+vb.w
                        + vc.x+vc.y+vc.z+vc.w + vd.x+vd.y+vd.z+vd.w;
                int t = sub * 16 + tl_r;
                float yv = (p + sep[t*16 + cl_r]) * sgp[t*16 + cl_r];
                size_t row = (size_t)bq * TSEQ + t0 + t;
                g_yh[row * D_INNER + d0 + cl_r] = __float2half(yv);
            }
            __syncthreads();
        }
    }
}

// ---------------- launch ----------------
extern "C" void kernel_launch(void* const* d_in, const int* in_sizes, int n_in,
                              void* d_out, int out_size) {
    (void)in_sizes; (void)n_in; (void)out_size;
    const float* x          = (const float*)d_in[0];
    const float* in_proj_w  = (const float*)d_in[1];
    const float* conv_w     = (const float*)d_in[2];
    const float* conv_b     = (const float*)d_in[3];
    const float* x_proj_w   = (const float*)d_in[4];
    const float* dt_proj_w  = (const float*)d_in[5];
    const float* dt_proj_b  = (const float*)d_in[6];
    const float* A_log      = (const float*)d_in[7];
    const float* Dp         = (const float*)d_in[8];
    const float* out_proj_w = (const float*)d_in[9];
    const float* norm_w     = (const float*)d_in[10];
    float* out = (float*)d_out;

    fp16 *xnh, *inwh, *xpwh, *dtwh, *opwh, *xch, *dth, *yh, *dch, *sgh;
    float *xzx, *xpp;
    cudaGetSymbolAddress((void**)&xnh,  g_xnh);
    cudaGetSymbolAddress((void**)&inwh, g_inwh);
    cudaGetSymbolAddress((void**)&xpwh, g_xpwh);
    cudaGetSymbolAddress((void**)&dtwh, g_dtwh);
    cudaGetSymbolAddress((void**)&opwh, g_opwh);
    cudaGetSymbolAddress((void**)&xch,  g_xch);
    cudaGetSymbolAddress((void**)&dth,  g_dth);
    cudaGetSymbolAddress((void**)&yh,   g_yh);
    cudaGetSymbolAddress((void**)&dch,  g_dch);
    cudaGetSymbolAddress((void**)&sgh,  g_sgh);
    cudaGetSymbolAddress((void**)&xzx,  g_xzx);
    cudaGetSymbolAddress((void**)&xpp,  g_xpp);

    cudaFuncSetAttribute((const void*)gemm_mma<0>, cudaFuncAttributeMaxDynamicSharedMemorySize, GSMEM);
    cudaFuncSetAttribute((const void*)gemm_mma<1>, cudaFuncAttributeMaxDynamicSharedMemorySize, GSMEM);
    cudaFuncSetAttribute((const void*)gemm_mma<2>, cudaFuncAttributeMaxDynamicSharedMemorySize, GSMEM);
    cudaFuncSetAttribute((const void*)gemm_mma<4>, cudaFuncAttributeMaxDynamicSharedMemorySize, GSMEM);
    cudaFuncSetAttribute((const void*)scan_kernel, cudaFuncAttributeMaxDynamicSharedMemorySize, SCAN_SMEM);

    // 1-3. weight prep + rmsnorm
    wprep_in<<<(C1 + 255)/256, 256>>>((const float4*)in_proj_w);
    wprep_rest<<<(CR + 255)/256, 256>>>((const float4*)out_proj_w,
                                        (const float4*)x_proj_w,
                                        (const float4*)dt_proj_w);
    rmsnorm_kernel<<<MROWS, 256>>>(x, norm_w);

    // 4. in_proj (profiler slot 4): x-half -> xzx fp32, z-half -> silu fp16
    gemm_mma<0><<<dim3(32, 32, 1), 256, GSMEM>>>(xnh, inwh,
        D_MODEL, 2*D_INNER, 2*D_INNER, xzx, nullptr, sgh);

    // 5. tiled conv + silu -> xch fp16
    conv_tiled<<<(MROWS/64) * 16, 256>>>(conv_w, conv_b);

    // 6. x_proj (1-term, split-K=8 -> partial buffers)
    gemm_mma<4><<<dim3(1, 32, XP_SPLIT), 256, GSMEM>>>(xch, xpwh,
        D_INNER, 96, 96, xpp, nullptr, nullptr);

    // 7. reduce partials -> xdbc + dt fp16
    xp_reduce_kernel<<<(MROWS*96 + 255)/256, 256>>>();

    // 8. dt_proj (1-term) + fast softplus/clip -> dc fp16
    gemm_mma<1><<<dim3(16, 32, 1), 256, GSMEM>>>(dth, dtwh,
        DT_RANK, D_INNER, D_INNER, nullptr, dt_proj_b, dch);

    // 9. selective scan (cp.async double-buffered staging)
    scan_kernel<<<NB * (D_INNER/16), 256, SCAN_SMEM>>>(A_log, Dp);

    // 10. out_proj (1-term fp16) + residual
    gemm_mma<2><<<dim3(8, 32, 1), 256, GSMEM>>>(yh, opwh,
        D_INNER, D_MODEL, D_MODEL, out, x, nullptr);
}